// round 8
// baseline (speedup 1.0000x reference)
#include <cuda_runtime.h>

typedef unsigned long long ull;
#define HWPX 65536
#define IMG  256
#define NCLS 6

// ---- scratch (__device__ globals; no allocations) ----
__device__ float g_qk  [(size_t)NCLS*128*HWPX];
__device__ float g_v   [(size_t)NCLS*64*HWPX];
__device__ float g_xo  [(size_t)NCLS*64*HWPX];
__device__ float g_x112[(size_t)NCLS*64*HWPX];
__device__ float g_x223[(size_t)NCLS*64*HWPX];
__device__ float g_x33 [(size_t)NCLS*64*HWPX];
__device__ float g_mask[(size_t)NCLS*65536];
__device__ float g_good[(size_t)NCLS*65536];
__device__ float g_rbar[NCLS*64];
__device__ float g_wT  [(size_t)NCLS*6*4*144*64];   // transposed conv3x3 weights

__device__ __forceinline__ ull ffma2(ull a, ull b, ull c){
    ull d; asm("fma.rn.f32x2 %0, %1, %2, %3;" : "=l"(d) : "l"(a), "l"(b), "l"(c)); return d;
}
__device__ __forceinline__ ull splat2(float v){
    ull d; unsigned u = __float_as_uint(v);
    asm("mov.b64 %0, {%1, %1};" : "=l"(d) : "r"(u)); return d;
}
__device__ __forceinline__ float2 unpk(ull a){
    unsigned lo, hi; asm("mov.b64 {%0, %1}, %2;" : "=r"(lo), "=r"(hi) : "l"(a));
    return make_float2(__uint_as_float(lo), __uint_as_float(hi));
}
__device__ __forceinline__ void cp16(float* smem_dst, const float* gsrc){
    unsigned d = (unsigned)__cvta_generic_to_shared(smem_dst);
    asm volatile("cp.async.ca.shared.global [%0], [%1], 16;" :: "r"(d), "l"(gsrc));
}

// ---- 1x1 conv + BN + ReLU ----
template<int OC>
__global__ __launch_bounds__(256)
void conv1x1_k(const float* __restrict__ x, const float* __restrict__ W,
               const float* __restrict__ S, const float* __restrict__ Bb,
               float* __restrict__ out)
{
    constexpr int P = OC + 4, OCG = OC/8, PXG = 256/OCG;
    __shared__ float ws[64*P];
    const int c = blockIdx.y;
    const float* Wc = W + (size_t)c*OC*64;
    for (int l = threadIdx.x; l < 64*OC; l += 256) {
        int oc = l>>6, ic = l&63; ws[ic*P+oc] = Wc[(size_t)oc*64+ic];
    }
    __syncthreads();
    const int ocg = threadIdx.x / PXG, pxg = threadIdx.x % PXG;
    const int px = blockIdx.x*(PXG*8) + pxg*8;
    const float* X = x + (size_t)c*64*HWPX + px;
    ull acc[4][8];
#pragma unroll
    for (int p=0;p<4;p++)
#pragma unroll
        for (int j=0;j<8;j++) acc[p][j]=0ull;
#pragma unroll 4
    for (int ic=0; ic<64; ic++) {
        float4 xa = *(const float4*)(X + (size_t)ic*HWPX);
        float4 xb = *(const float4*)(X + (size_t)ic*HWPX + 4);
        ull sv[8] = { splat2(xa.x),splat2(xa.y),splat2(xa.z),splat2(xa.w),
                      splat2(xb.x),splat2(xb.y),splat2(xb.z),splat2(xb.w) };
        const ull* wp = (const ull*)(ws + ic*P + ocg*8);
        ull w0=wp[0],w1=wp[1],w2=wp[2],w3=wp[3];
#pragma unroll
        for (int j=0;j<8;j++) {
            acc[0][j]=ffma2(w0,sv[j],acc[0][j]); acc[1][j]=ffma2(w1,sv[j],acc[1][j]);
            acc[2][j]=ffma2(w2,sv[j],acc[2][j]); acc[3][j]=ffma2(w3,sv[j],acc[3][j]);
        }
    }
    const float* Sc = S + (size_t)c*OC + ocg*8;
    const float* Bc = Bb + (size_t)c*OC + ocg*8;
    float* O = out + (size_t)c*OC*HWPX + px;
#pragma unroll
    for (int p=0;p<4;p++) {
        float s0=Sc[2*p],s1=Sc[2*p+1],b0=Bc[2*p],b1=Bc[2*p+1];
        float r0[8],r1[8];
#pragma unroll
        for (int j=0;j<8;j++) {
            float2 v = unpk(acc[p][j]);
            r0[j]=fmaxf(v.x*s0+b0,0.f); r1[j]=fmaxf(v.y*s1+b1,0.f);
        }
        float* O0 = O + (size_t)(ocg*8+2*p)*HWPX;
        float* O1 = O + (size_t)(ocg*8+2*p+1)*HWPX;
        *(float4*)O0     = make_float4(r0[0],r0[1],r0[2],r0[3]);
        *(float4*)(O0+4) = make_float4(r0[4],r0[5],r0[6],r0[7]);
        *(float4*)O1     = make_float4(r1[0],r1[1],r1[2],r1[3]);
        *(float4*)(O1+4) = make_float4(r1[4],r1[5],r1[6],r1[7]);
    }
}

// ---- rbar[c,k] = mean over (q,h) of rel bias ----
__global__ void rbar_k(const float* __restrict__ relb)
{
    int idx = blockIdx.x*64 + threadIdx.x;
    if (idx >= NCLS*64) return;
    int c = idx>>6, k = idx&63, ky = k>>3, kx = k&7;
    float s = 0.f;
    for (int q=0;q<64;q++) {
        int qy=q>>3, qx=q&7;
        const float* p = relb + (size_t)c*900 + ((qy-ky+7)*15 + (qx-kx+7))*4;
        s += p[0]+p[1]+p[2]+p[3];
    }
    g_rbar[idx] = s * (1.f/256.f);
}

// ---- per-window mean-dots mask ----
__global__ void mask_k()
{
    __shared__ float qw[64*65], kw[64*65], qs[64];
    const int c = blockIdx.y, n = blockIdx.x;
    const int wy = n>>5, wx = n&31, t = threadIdx.x;
    const int px = (wy*8 + (t>>3))*IMG + wx*8 + (t&7);
    const float* Q = g_qk + (size_t)c*128*HWPX;
    for (int ch=0; ch<64; ch++) {
        qw[ch*65+t] = Q[(size_t)ch*HWPX + px];
        kw[ch*65+t] = Q[(size_t)(64+ch)*HWPX + px];
    }
    __syncthreads();
    float s = 0.f;
    for (int q=0;q<64;q++) s += qw[t*65+q];
    qs[t] = s;
    __syncthreads();
    float m = 0.f;
    for (int ch=0;ch<64;ch++) m += qs[ch]*kw[ch*65+t];
    g_mask[(size_t)c*65536 + n*64 + t] = m*(0.25f/256.f) + g_rbar[c*64+t];
}

// ---- cross-class argmax -> +/-1 ----
__global__ void good_k()
{
    int idx = blockIdx.x*256 + threadIdx.x;
    float m[NCLS], mx = -1e30f;
#pragma unroll
    for (int c=0;c<NCLS;c++) { m[c]=g_mask[(size_t)c*65536+idx]; mx=fmaxf(mx,m[c]); }
#pragma unroll
    for (int c=0;c<NCLS;c++) g_good[(size_t)c*65536+idx] = (m[c]==mx)?1.f:-1.f;
}

// ---- fused window attention: dots->softmax->±mask->@v->+x ----
__global__ __launch_bounds__(256)
void attn_k(const float* __restrict__ x, const float* __restrict__ relb,
            float* __restrict__ xo)
{
    __shared__ float buf[4*64*16];
    __shared__ float rel_s[900];
    __shared__ float gg[64];
    const int c = blockIdx.y, n = blockIdx.x;
    const int wy = n>>5, wx = n&31, tid = threadIdx.x;
    for (int l=tid; l<900; l+=256) rel_s[l] = relb[(size_t)c*900+l];
    if (tid < 64) gg[tid] = g_good[(size_t)c*65536 + n*64 + tid];
    const float* Q = g_qk + (size_t)c*128*HWPX;
    for (int l=tid; l<4096; l+=256) {
        int pos=l&63, ch=l>>6;
        int gpx = (wy*8+(pos>>3))*IMG + wx*8 + (pos&7);
        buf[((ch>>4)*64+pos)*16 + (ch&15)] = Q[(size_t)ch*HWPX + gpx];
    }
    __syncthreads();
    const int h = tid>>6, q = tid&63;
    float qv[16];
#pragma unroll
    for (int d=0;d<16;d++) qv[d] = buf[(h*64+q)*16+d];
    __syncthreads();
    for (int l=tid; l<4096; l+=256) {
        int pos=l&63, ch=l>>6;
        int gpx = (wy*8+(pos>>3))*IMG + wx*8 + (pos&7);
        buf[((ch>>4)*64+pos)*16 + (ch&15)] = Q[(size_t)(64+ch)*HWPX + gpx];
    }
    __syncthreads();
    float dt[64];
    const int qy=q>>3, qx=q&7;
#pragma unroll
    for (int k=0;k<64;k++) {
        const float4* kp = (const float4*)(buf + (h*64+k)*16);
        float4 k0=kp[0],k1=kp[1],k2=kp[2],k3=kp[3];
        float a = qv[0]*k0.x+qv[1]*k0.y+qv[2]*k0.z+qv[3]*k0.w
                + qv[4]*k1.x+qv[5]*k1.y+qv[6]*k1.z+qv[7]*k1.w
                + qv[8]*k2.x+qv[9]*k2.y+qv[10]*k2.z+qv[11]*k2.w
                + qv[12]*k3.x+qv[13]*k3.y+qv[14]*k3.z+qv[15]*k3.w;
        int ky=k>>3, kx=k&7;
        dt[k] = a*0.25f + rel_s[((qy-ky+7)*15+(qx-kx+7))*4 + h];
    }
    float mx = -1e30f;
#pragma unroll
    for (int k=0;k<64;k++) mx = fmaxf(mx, dt[k]);
    float sum = 0.f;
#pragma unroll
    for (int k=0;k<64;k++) { dt[k]=__expf(dt[k]-mx); sum+=dt[k]; }
    float sc = gg[q]/sum;
#pragma unroll
    for (int k=0;k<64;k++) dt[k] *= sc*gg[k];
    __syncthreads();
    const float* V = g_v + (size_t)c*64*HWPX;
    for (int l=tid; l<4096; l+=256) {
        int pos=l&63, ch=l>>6;
        int gpx = (wy*8+(pos>>3))*IMG + wx*8 + (pos&7);
        buf[((ch>>4)*64+pos)*16 + (ch&15)] = V[(size_t)ch*HWPX + gpx];
    }
    __syncthreads();
    float o[16];
#pragma unroll
    for (int d=0;d<16;d++) o[d]=0.f;
#pragma unroll
    for (int k=0;k<64;k++) {
        float a = dt[k];
        const float4* vp = (const float4*)(buf + (h*64+k)*16);
        float4 v0=vp[0],v1=vp[1],v2=vp[2],v3=vp[3];
        o[0]+=a*v0.x; o[1]+=a*v0.y; o[2]+=a*v0.z; o[3]+=a*v0.w;
        o[4]+=a*v1.x; o[5]+=a*v1.y; o[6]+=a*v1.z; o[7]+=a*v1.w;
        o[8]+=a*v2.x; o[9]+=a*v2.y; o[10]+=a*v2.z; o[11]+=a*v2.w;
        o[12]+=a*v3.x; o[13]+=a*v3.y; o[14]+=a*v3.z; o[15]+=a*v3.w;
    }
    const int gpx = (wy*8+qy)*IMG + wx*8 + qx;
    const float* X = x + (size_t)c*64*HWPX;
    float* O = xo + (size_t)c*64*HWPX;
#pragma unroll
    for (int d=0;d<16;d++) {
        size_t off = (size_t)(h*16+d)*HWPX + gpx;
        O[off] = X[off] + o[d];
    }
}

// ---- one-time weight transpose: [cs][oc][576] -> [cs][icc][within(144)][oc(64)] ----
__global__ void wT_k(const float* __restrict__ W)
{
    int i = blockIdx.x*256 + threadIdx.x;
    if (i >= NCLS*6*4*144*64) return;
    int oc = i & 63; int rest = i >> 6;
    int within = rest % 144; rest /= 144;
    int icc = rest & 3; int cs = rest >> 2;
    g_wT[i] = W[(size_t)cs*36864 + (size_t)oc*576 + icc*144 + within];
}

// ---- multi-branch 3x3 conv: dst = sum_sub clip6(conv3x3(src)+BN) ----
// tile 8 rows x 32 cols, 512 threads; weights double-buffered via cp.async.
// dyn smem: in_s 64*10*36 + 2*9216 weight bufs = (23040+18432)*4 = 165888 B
#define C3_IN (64*10*36)
__global__ __launch_bounds__(512,1)
void conv3x3_k(const float* __restrict__ src, const float* __restrict__ S,
               const float* __restrict__ Bb, float* __restrict__ dst,
               int nsub, int sub0)
{
    extern __shared__ float sm[];
    float* in_s = sm;                 // [64][10][36]
    float* wbuf0 = sm + C3_IN;        // [9216]
    float* wbuf1 = wbuf0 + 9216;
    const int c = blockIdx.z, r0 = blockIdx.y*8, c0 = blockIdx.x*32;
    const int tid = threadIdx.x;
    const float* SRC = src + (size_t)c*64*HWPX;
    for (int idx = tid; idx < 64*10*34; idx += 512) {
        int col = idx % 34; int rest = idx / 34; int lr = rest % 10; int ic = rest / 10;
        int gr = r0-1+lr, gc = c0-1+col;
        float v = 0.f;
        if ((unsigned)gr<256u && (unsigned)gc<256u) v = SRC[(size_t)ic*HWPX + gr*IMG + gc];
        in_s[(ic*10+lr)*36 + col] = v;
    }
    const int ocg = tid>>6;           // 0..7 (constant per warp-pair -> weight broadcast)
    const int pxg = tid&63;
    const int row = pxg>>3, colg = pxg&7;
    float osum[8][4];
#pragma unroll
    for (int a=0;a<8;a++)
#pragma unroll
        for (int j=0;j<4;j++) osum[a][j]=0.f;

    for (int sub=0; sub<nsub; sub++) {
        const float* G = g_wT + (size_t)(c*6+sub0+sub)*4*9216;
        // prefetch icc=0
        for (int l = tid; l < 2304; l += 512) cp16(wbuf0 + l*4, G + l*4);
        asm volatile("cp.async.commit_group;");
        ull acc[4][4];
#pragma unroll
        for (int p=0;p<4;p++)
#pragma unroll
            for (int j=0;j<4;j++) acc[p][j]=0ull;

        for (int icc=0; icc<4; icc++) {
            float* wb = (icc & 1) ? wbuf1 : wbuf0;
            if (icc < 3) {
                float* wn = (icc & 1) ? wbuf0 : wbuf1;
                const float* Gn = G + (size_t)(icc+1)*9216;
                for (int l = tid; l < 2304; l += 512) cp16(wn + l*4, Gn + l*4);
                asm volatile("cp.async.commit_group;");
                asm volatile("cp.async.wait_group 1;");
            } else {
                asm volatile("cp.async.wait_group 0;");
            }
            __syncthreads();
#pragma unroll 4
            for (int icl=0; icl<16; icl++) {
                const float* ibase = in_s + ((icc*16+icl)*10 + row)*36 + colg*4;
#pragma unroll
                for (int ky=0; ky<3; ky++) {
                    const float* ip = ibase + ky*36;
                    float4 ia = *(const float4*)ip;
                    float2 ib = *(const float2*)(ip+4);
                    ull sv[6] = { splat2(ia.x),splat2(ia.y),splat2(ia.z),
                                  splat2(ia.w),splat2(ib.x),splat2(ib.y) };
                    const float* wrow = wb + (icl*9+ky*3)*64 + ocg*8;
#pragma unroll
                    for (int kx=0; kx<3; kx++) {
                        const ull* wp = (const ull*)(wrow + kx*64);
                        ull w0=wp[0],w1=wp[1],w2=wp[2],w3=wp[3];
#pragma unroll
                        for (int j=0;j<4;j++) {
                            acc[0][j]=ffma2(w0,sv[kx+j],acc[0][j]);
                            acc[1][j]=ffma2(w1,sv[kx+j],acc[1][j]);
                            acc[2][j]=ffma2(w2,sv[kx+j],acc[2][j]);
                            acc[3][j]=ffma2(w3,sv[kx+j],acc[3][j]);
                        }
                    }
                }
            }
            __syncthreads();
        }
        const float* Sc = S + (size_t)(c*6+sub0+sub)*64 + ocg*8;
        const float* Bc = Bb + (size_t)(c*6+sub0+sub)*64 + ocg*8;
#pragma unroll
        for (int p=0;p<4;p++) {
            float s0=Sc[2*p],s1=Sc[2*p+1],b0=Bc[2*p],b1=Bc[2*p+1];
#pragma unroll
            for (int j=0;j<4;j++) {
                float2 v = unpk(acc[p][j]);
                osum[2*p][j]   += fminf(fmaxf(v.x*s0+b0,0.f),6.f);
                osum[2*p+1][j] += fminf(fmaxf(v.y*s1+b1,0.f),6.f);
            }
        }
    }
    float* D = dst + (size_t)c*64*HWPX + (r0+row)*IMG + c0 + colg*4;
#pragma unroll
    for (int a=0;a<8;a++)
        *(float4*)(D + (size_t)(ocg*8+a)*HWPX) =
            make_float4(osum[a][0],osum[a][1],osum[a][2],osum[a][3]);
}

// ---- cat 1x1 conv + BN + residual + relu -> d_out ----
__global__ __launch_bounds__(256)
void cat_k(const float* __restrict__ cw, const float* __restrict__ cs,
           const float* __restrict__ cb, float* __restrict__ out)
{
    __shared__ float ws[64*68];
    const int c = blockIdx.y, tid = threadIdx.x;
    const int ocg = tid>>5, pxg = tid&31;
    const int px = blockIdx.x*256 + pxg*8;
    ull acc[4][8];
#pragma unroll
    for (int p=0;p<4;p++)
#pragma unroll
        for (int j=0;j<8;j++) acc[p][j]=0ull;
    const float* srcs[3] = { g_x112 + (size_t)c*64*HWPX,
                             g_x223 + (size_t)c*64*HWPX,
                             g_x33  + (size_t)c*64*HWPX };
    for (int s=0; s<3; s++) {
        __syncthreads();
        for (int l=tid; l<4096; l+=256) {
            int oc=l>>6, ic=l&63;
            ws[ic*68+oc] = cw[(size_t)c*64*192 + oc*192 + s*64 + ic];
        }
        __syncthreads();
        const float* X = srcs[s] + px;
#pragma unroll 4
        for (int ic=0; ic<64; ic++) {
            float4 xa = *(const float4*)(X + (size_t)ic*HWPX);
            float4 xb = *(const float4*)(X + (size_t)ic*HWPX + 4);
            ull sv[8] = { splat2(xa.x),splat2(xa.y),splat2(xa.z),splat2(xa.w),
                          splat2(xb.x),splat2(xb.y),splat2(xb.z),splat2(xb.w) };
            const ull* wp = (const ull*)(ws + ic*68 + ocg*8);
            ull w0=wp[0],w1=wp[1],w2=wp[2],w3=wp[3];
#pragma unroll
            for (int j=0;j<8;j++) {
                acc[0][j]=ffma2(w0,sv[j],acc[0][j]); acc[1][j]=ffma2(w1,sv[j],acc[1][j]);
                acc[2][j]=ffma2(w2,sv[j],acc[2][j]); acc[3][j]=ffma2(w3,sv[j],acc[3][j]);
            }
        }
    }
    const float* Sc = cs + (size_t)c*64 + ocg*8;
    const float* Bc = cb + (size_t)c*64 + ocg*8;
    const float* XO = g_xo + (size_t)c*64*HWPX + px;
    float* O = out + (size_t)c*64*HWPX + px;
#pragma unroll
    for (int p=0;p<4;p++) {
        float s0=Sc[2*p],s1=Sc[2*p+1],b0=Bc[2*p],b1=Bc[2*p+1];
#pragma unroll
        for (int j=0;j<8;j++) {
            float2 v = unpk(acc[p][j]);
            size_t o0 = (size_t)(ocg*8+2*p)*HWPX + j;
            size_t o1 = (size_t)(ocg*8+2*p+1)*HWPX + j;
            O[o0] = fmaxf(v.x*s0+b0 + XO[o0], 0.f);
            O[o1] = fmaxf(v.y*s1+b1 + XO[o1], 0.f);
        }
    }
}

extern "C" void kernel_launch(void* const* d_in, const int* in_sizes, int n_in,
                              void* d_out, int out_size)
{
    const float* x    = (const float*)d_in[0];
    const float* qkw  = (const float*)d_in[1];
    const float* qks  = (const float*)d_in[2];
    const float* qkb  = (const float*)d_in[3];
    const float* relb = (const float*)d_in[4];
    const float* wvw  = (const float*)d_in[5];
    const float* wvs  = (const float*)d_in[6];
    const float* wvb  = (const float*)d_in[7];
    const float* mmsw = (const float*)d_in[8];
    const float* mmss = (const float*)d_in[9];
    const float* mmsb = (const float*)d_in[10];
    const float* catw = (const float*)d_in[11];
    const float* cats = (const float*)d_in[12];
    const float* catb = (const float*)d_in[13];
    float* out = (float*)d_out;

    float *qk, *v, *xo, *a112, *b223, *c33;
    cudaGetSymbolAddress((void**)&qk,   g_qk);
    cudaGetSymbolAddress((void**)&v,    g_v);
    cudaGetSymbolAddress((void**)&xo,   g_xo);
    cudaGetSymbolAddress((void**)&a112, g_x112);
    cudaGetSymbolAddress((void**)&b223, g_x223);
    cudaGetSymbolAddress((void**)&c33,  g_x33);

    const int C3_SMEM = (C3_IN + 2*9216) * 4;   // 165888 B
    cudaFuncSetAttribute(conv3x3_k, cudaFuncAttributeMaxDynamicSharedMemorySize, C3_SMEM);

    conv1x1_k<128><<<dim3(512, NCLS), 256>>>(x, qkw, qks, qkb, qk);
    conv1x1_k<64> <<<dim3(256, NCLS), 256>>>(x, wvw, wvs, wvb, v);
    rbar_k<<<NCLS, 64>>>(relb);
    mask_k<<<dim3(1024, NCLS), 64>>>();
    good_k<<<256, 256>>>();
    attn_k<<<dim3(1024, NCLS), 256>>>(x, relb, xo);
    wT_k<<<(NCLS*6*4*144*64 + 255)/256, 256>>>(mmsw);
    conv3x3_k<<<dim3(8, 32, NCLS), 512, C3_SMEM>>>(xo,   mmss, mmsb, a112, 3, 0);
    conv3x3_k<<<dim3(8, 32, NCLS), 512, C3_SMEM>>>(a112, mmss, mmsb, b223, 2, 3);
    conv3x3_k<<<dim3(8, 32, NCLS), 512, C3_SMEM>>>(b223, mmss, mmsb, c33,  1, 5);
    cat_k<<<dim3(256, NCLS), 256>>>(catw, cats, catb, out);
}

// round 9
// speedup vs baseline: 1.4224x; 1.4224x over previous
#include <cuda_runtime.h>
#include <cuda_bf16.h>

typedef unsigned long long ull;
#define HWPX 65536
#define IMG  256
#define NCLS 6
#define SWZ(o) ((unsigned)(o) ^ ((((unsigned)(o))>>3)&0x70))

// ---- scratch ----
__device__ float g_qk  [(size_t)NCLS*128*HWPX];
__device__ float g_v   [(size_t)NCLS*64*HWPX];
__device__ float g_xo  [(size_t)NCLS*64*HWPX];
__device__ float g_x112[(size_t)NCLS*64*HWPX];
__device__ float g_x223[(size_t)NCLS*64*HWPX];
__device__ float g_x33 [(size_t)NCLS*64*HWPX];
__device__ float g_mask[(size_t)NCLS*65536];
__device__ float g_good[(size_t)NCLS*65536];
__device__ float g_rbar[NCLS*64];
// channel-last bf16 hi/lo activations: [cls][px(65536)][ic(64)]
__device__ __nv_bfloat16 g_h0[(size_t)NCLS*HWPX*64], g_l0[(size_t)NCLS*HWPX*64];
__device__ __nv_bfloat16 g_h1[(size_t)NCLS*HWPX*64], g_l1[(size_t)NCLS*HWPX*64];
__device__ __nv_bfloat16 g_h2[(size_t)NCLS*HWPX*64], g_l2[(size_t)NCLS*HWPX*64];
// conv weights bf16 hi/lo: [cs(36)][kyx(9)][ic(64)][oc(64)]
__device__ __nv_bfloat16 g_wbh[(size_t)36*9*64*64], g_wbl[(size_t)36*9*64*64];

__device__ __forceinline__ ull ffma2(ull a, ull b, ull c){
    ull d; asm("fma.rn.f32x2 %0, %1, %2, %3;" : "=l"(d) : "l"(a), "l"(b), "l"(c)); return d;
}
__device__ __forceinline__ ull splat2(float v){
    ull d; unsigned u = __float_as_uint(v);
    asm("mov.b64 %0, {%1, %1};" : "=l"(d) : "r"(u)); return d;
}
__device__ __forceinline__ float2 unpk(ull a){
    unsigned lo, hi; asm("mov.b64 {%0, %1}, %2;" : "=r"(lo), "=r"(hi) : "l"(a));
    return make_float2(__uint_as_float(lo), __uint_as_float(hi));
}
__device__ __forceinline__ void cp16(void* smem_dst, const void* gsrc){
    unsigned d = (unsigned)__cvta_generic_to_shared(smem_dst);
    asm volatile("cp.async.ca.shared.global [%0], [%1], 16;" :: "r"(d), "l"(gsrc));
}
__device__ __forceinline__ unsigned sptr(const void* p){ return (unsigned)__cvta_generic_to_shared(p); }
__device__ __forceinline__ void ldmA(unsigned* r, unsigned a){
    asm volatile("ldmatrix.sync.aligned.m8n8.x4.shared.b16 {%0,%1,%2,%3},[%4];"
        :"=r"(r[0]),"=r"(r[1]),"=r"(r[2]),"=r"(r[3]):"r"(a));
}
__device__ __forceinline__ void ldmBT(unsigned* r, unsigned a){
    asm volatile("ldmatrix.sync.aligned.m8n8.x4.trans.shared.b16 {%0,%1,%2,%3},[%4];"
        :"=r"(r[0]),"=r"(r[1]),"=r"(r[2]),"=r"(r[3]):"r"(a));
}
__device__ __forceinline__ void mmabf(float* c, const unsigned* a, const unsigned* b){
    asm volatile("mma.sync.aligned.m16n8k16.row.col.f32.bf16.bf16.f32 "
        "{%0,%1,%2,%3},{%4,%5,%6,%7},{%8,%9},{%0,%1,%2,%3};"
        :"+f"(c[0]),"+f"(c[1]),"+f"(c[2]),"+f"(c[3])
        :"r"(a[0]),"r"(a[1]),"r"(a[2]),"r"(a[3]),"r"(b[0]),"r"(b[1]));
}
__device__ __forceinline__ unsigned packbf(float a, float b){
    __nv_bfloat16 ha=__float2bfloat16(a), hb=__float2bfloat16(b);
    return (unsigned)__bfloat16_as_ushort(ha) | ((unsigned)__bfloat16_as_ushort(hb)<<16);
}

// ---- 1x1 conv + BN + ReLU ----
template<int OC>
__global__ __launch_bounds__(256)
void conv1x1_k(const float* __restrict__ x, const float* __restrict__ W,
               const float* __restrict__ S, const float* __restrict__ Bb,
               float* __restrict__ out)
{
    constexpr int P = OC + 4, OCG = OC/8, PXG = 256/OCG;
    __shared__ float ws[64*P];
    const int c = blockIdx.y;
    const float* Wc = W + (size_t)c*OC*64;
    for (int l = threadIdx.x; l < 64*OC; l += 256) {
        int oc = l>>6, ic = l&63; ws[ic*P+oc] = Wc[(size_t)oc*64+ic];
    }
    __syncthreads();
    const int ocg = threadIdx.x / PXG, pxg = threadIdx.x % PXG;
    const int px = blockIdx.x*(PXG*8) + pxg*8;
    const float* X = x + (size_t)c*64*HWPX + px;
    ull acc[4][8];
#pragma unroll
    for (int p=0;p<4;p++)
#pragma unroll
        for (int j=0;j<8;j++) acc[p][j]=0ull;
#pragma unroll 4
    for (int ic=0; ic<64; ic++) {
        float4 xa = *(const float4*)(X + (size_t)ic*HWPX);
        float4 xb = *(const float4*)(X + (size_t)ic*HWPX + 4);
        ull sv[8] = { splat2(xa.x),splat2(xa.y),splat2(xa.z),splat2(xa.w),
                      splat2(xb.x),splat2(xb.y),splat2(xb.z),splat2(xb.w) };
        const ull* wp = (const ull*)(ws + ic*P + ocg*8);
        ull w0=wp[0],w1=wp[1],w2=wp[2],w3=wp[3];
#pragma unroll
        for (int j=0;j<8;j++) {
            acc[0][j]=ffma2(w0,sv[j],acc[0][j]); acc[1][j]=ffma2(w1,sv[j],acc[1][j]);
            acc[2][j]=ffma2(w2,sv[j],acc[2][j]); acc[3][j]=ffma2(w3,sv[j],acc[3][j]);
        }
    }
    const float* Sc = S + (size_t)c*OC + ocg*8;
    const float* Bc = Bb + (size_t)c*OC + ocg*8;
    float* O = out + (size_t)c*OC*HWPX + px;
#pragma unroll
    for (int p=0;p<4;p++) {
        float s0=Sc[2*p],s1=Sc[2*p+1],b0=Bc[2*p],b1=Bc[2*p+1];
        float r0[8],r1[8];
#pragma unroll
        for (int j=0;j<8;j++) {
            float2 v = unpk(acc[p][j]);
            r0[j]=fmaxf(v.x*s0+b0,0.f); r1[j]=fmaxf(v.y*s1+b1,0.f);
        }
        float* O0 = O + (size_t)(ocg*8+2*p)*HWPX;
        float* O1 = O + (size_t)(ocg*8+2*p+1)*HWPX;
        *(float4*)O0     = make_float4(r0[0],r0[1],r0[2],r0[3]);
        *(float4*)(O0+4) = make_float4(r0[4],r0[5],r0[6],r0[7]);
        *(float4*)O1     = make_float4(r1[0],r1[1],r1[2],r1[3]);
        *(float4*)(O1+4) = make_float4(r1[4],r1[5],r1[6],r1[7]);
    }
}

__global__ void rbar_k(const float* __restrict__ relb)
{
    int idx = blockIdx.x*64 + threadIdx.x;
    if (idx >= NCLS*64) return;
    int c = idx>>6, k = idx&63, ky = k>>3, kx = k&7;
    float s = 0.f;
    for (int q=0;q<64;q++) {
        int qy=q>>3, qx=q&7;
        const float* p = relb + (size_t)c*900 + ((qy-ky+7)*15 + (qx-kx+7))*4;
        s += p[0]+p[1]+p[2]+p[3];
    }
    g_rbar[idx] = s * (1.f/256.f);
}

__global__ void mask_k()
{
    __shared__ float qw[64*65], kw[64*65], qs[64];
    const int c = blockIdx.y, n = blockIdx.x;
    const int wy = n>>5, wx = n&31, t = threadIdx.x;
    const int px = (wy*8 + (t>>3))*IMG + wx*8 + (t&7);
    const float* Q = g_qk + (size_t)c*128*HWPX;
    for (int ch=0; ch<64; ch++) {
        qw[ch*65+t] = Q[(size_t)ch*HWPX + px];
        kw[ch*65+t] = Q[(size_t)(64+ch)*HWPX + px];
    }
    __syncthreads();
    float s = 0.f;
    for (int q=0;q<64;q++) s += qw[t*65+q];
    qs[t] = s;
    __syncthreads();
    float m = 0.f;
    for (int ch=0;ch<64;ch++) m += qs[ch]*kw[ch*65+t];
    g_mask[(size_t)c*65536 + n*64 + t] = m*(0.25f/256.f) + g_rbar[c*64+t];
}

__global__ void good_k()
{
    int idx = blockIdx.x*256 + threadIdx.x;
    float m[NCLS], mx = -1e30f;
#pragma unroll
    for (int c=0;c<NCLS;c++) { m[c]=g_mask[(size_t)c*65536+idx]; mx=fmaxf(mx,m[c]); }
#pragma unroll
    for (int c=0;c<NCLS;c++) g_good[(size_t)c*65536+idx] = (m[c]==mx)?1.f:-1.f;
}

__global__ __launch_bounds__(256)
void attn_k(const float* __restrict__ x, const float* __restrict__ relb,
            float* __restrict__ xo)
{
    __shared__ float buf[4*64*16];
    __shared__ float rel_s[900];
    __shared__ float gg[64];
    const int c = blockIdx.y, n = blockIdx.x;
    const int wy = n>>5, wx = n&31, tid = threadIdx.x;
    for (int l=tid; l<900; l+=256) rel_s[l] = relb[(size_t)c*900+l];
    if (tid < 64) gg[tid] = g_good[(size_t)c*65536 + n*64 + tid];
    const float* Q = g_qk + (size_t)c*128*HWPX;
    for (int l=tid; l<4096; l+=256) {
        int pos=l&63, ch=l>>6;
        int gpx = (wy*8+(pos>>3))*IMG + wx*8 + (pos&7);
        buf[((ch>>4)*64+pos)*16 + (ch&15)] = Q[(size_t)ch*HWPX + gpx];
    }
    __syncthreads();
    const int h = tid>>6, q = tid&63;
    float qv[16];
#pragma unroll
    for (int d=0;d<16;d++) qv[d] = buf[(h*64+q)*16+d];
    __syncthreads();
    for (int l=tid; l<4096; l+=256) {
        int pos=l&63, ch=l>>6;
        int gpx = (wy*8+(pos>>3))*IMG + wx*8 + (pos&7);
        buf[((ch>>4)*64+pos)*16 + (ch&15)] = Q[(size_t)(64+ch)*HWPX + gpx];
    }
    __syncthreads();
    float dt[64];
    const int qy=q>>3, qx=q&7;
#pragma unroll
    for (int k=0;k<64;k++) {
        const float4* kp = (const float4*)(buf + (h*64+k)*16);
        float4 k0=kp[0],k1=kp[1],k2=kp[2],k3=kp[3];
        float a = qv[0]*k0.x+qv[1]*k0.y+qv[2]*k0.z+qv[3]*k0.w
                + qv[4]*k1.x+qv[5]*k1.y+qv[6]*k1.z+qv[7]*k1.w
                + qv[8]*k2.x+qv[9]*k2.y+qv[10]*k2.z+qv[11]*k2.w
                + qv[12]*k3.x+qv[13]*k3.y+qv[14]*k3.z+qv[15]*k3.w;
        int ky=k>>3, kx=k&7;
        dt[k] = a*0.25f + rel_s[((qy-ky+7)*15+(qx-kx+7))*4 + h];
    }
    float mx = -1e30f;
#pragma unroll
    for (int k=0;k<64;k++) mx = fmaxf(mx, dt[k]);
    float sum = 0.f;
#pragma unroll
    for (int k=0;k<64;k++) { dt[k]=__expf(dt[k]-mx); sum+=dt[k]; }
    float sc = gg[q]/sum;
#pragma unroll
    for (int k=0;k<64;k++) dt[k] *= sc*gg[k];
    __syncthreads();
    const float* V = g_v + (size_t)c*64*HWPX;
    for (int l=tid; l<4096; l+=256) {
        int pos=l&63, ch=l>>6;
        int gpx = (wy*8+(pos>>3))*IMG + wx*8 + (pos&7);
        buf[((ch>>4)*64+pos)*16 + (ch&15)] = V[(size_t)ch*HWPX + gpx];
    }
    __syncthreads();
    float o[16];
#pragma unroll
    for (int d=0;d<16;d++) o[d]=0.f;
#pragma unroll
    for (int k=0;k<64;k++) {
        float a = dt[k];
        const float4* vp = (const float4*)(buf + (h*64+k)*16);
        float4 v0=vp[0],v1=vp[1],v2=vp[2],v3=vp[3];
        o[0]+=a*v0.x; o[1]+=a*v0.y; o[2]+=a*v0.z; o[3]+=a*v0.w;
        o[4]+=a*v1.x; o[5]+=a*v1.y; o[6]+=a*v1.z; o[7]+=a*v1.w;
        o[8]+=a*v2.x; o[9]+=a*v2.y; o[10]+=a*v2.z; o[11]+=a*v2.w;
        o[12]+=a*v3.x; o[13]+=a*v3.y; o[14]+=a*v3.z; o[15]+=a*v3.w;
    }
    const int gpx = (wy*8+qy)*IMG + wx*8 + qx;
    const float* X = x + (size_t)c*64*HWPX;
    float* O = xo + (size_t)c*64*HWPX;
    float r[16];
#pragma unroll
    for (int d=0;d<16;d++) {
        size_t off = (size_t)(h*16+d)*HWPX + gpx;
        r[d] = X[off] + o[d];
        O[off] = r[d];
    }
    // channel-last bf16 hi/lo
    unsigned ph[8], pl[8];
#pragma unroll
    for (int d=0;d<8;d++) {
        float a = r[2*d], b = r[2*d+1];
        __nv_bfloat16 ha=__float2bfloat16(a), hb=__float2bfloat16(b);
        float la = a - __bfloat162float(ha), lb = b - __bfloat162float(hb);
        ph[d] = (unsigned)__bfloat16_as_ushort(ha) | ((unsigned)__bfloat16_as_ushort(hb)<<16);
        pl[d] = packbf(la, lb);
    }
    size_t co = ((size_t)(c<<16) + gpx)*64 + h*16;
    *(uint4*)(g_h0+co)   = make_uint4(ph[0],ph[1],ph[2],ph[3]);
    *(uint4*)(g_h0+co+8) = make_uint4(ph[4],ph[5],ph[6],ph[7]);
    *(uint4*)(g_l0+co)   = make_uint4(pl[0],pl[1],pl[2],pl[3]);
    *(uint4*)(g_l0+co+8) = make_uint4(pl[4],pl[5],pl[6],pl[7]);
}

// ---- weight prep: f32 [cs][oc][ic][3][3] -> bf16 hi/lo [cs][kyx][ic][oc] ----
__global__ void wprep_k(const float* __restrict__ W)
{
    int i = blockIdx.x*256 + threadIdx.x;
    if (i >= 36*9*64*64) return;
    int kyx = i % 9; int t = i / 9;
    int ic = t & 63; t >>= 6;
    int oc = t & 63; int cs = t >> 6;
    float w = W[(((size_t)cs*64 + oc)*64 + ic)*9 + kyx];
    __nv_bfloat16 h = __float2bfloat16(w);
    float l = w - __bfloat162float(h);
    size_t d = ((size_t)cs*9 + kyx)*4096 + ic*64 + oc;
    g_wbh[d] = h; g_wbl[d] = __float2bfloat16(l);
}

// ---- conv3x3 via bf16 mma 3-pass split ----
#define C3_HALF 41984
#define C3_SMEMB (2*C3_HALF + 4*2048)   // 92160
__global__ __launch_bounds__(512,1)
void c3mma_k(const __nv_bfloat16* __restrict__ srcH, const __nv_bfloat16* __restrict__ srcL,
             const float* __restrict__ S, const float* __restrict__ Bb,
             float* __restrict__ dstF, __nv_bfloat16* __restrict__ dstH,
             __nv_bfloat16* __restrict__ dstL, int nsub, int sub0)
{
    extern __shared__ char sm[];
    char* inH = sm; char* inL = sm + C3_HALF;
    char* wb  = sm + 2*C3_HALF;                 // [buf2][half2][2048]
    const int cls = blockIdx.z, ty = blockIdx.y, tx = blockIdx.x;
    const int tid = threadIdx.x, lane = tid&31, wid = tid>>5;
    const int mb = wid&7, nb = wid>>3;

    // stage halo 18x18 px x 64ic (swizzled rows of 128B)
    for (int idx = tid; idx < 324*8; idx += 512) {
        int p = idx>>3, ch = idx&7;
        int gy = ty*16 - 1 + p/18, gx = tx*16 - 1 + p%18;
        unsigned d = SWZ(p*128 + ch*16);
        if ((unsigned)gy<256u && (unsigned)gx<256u) {
            size_t so = ((size_t)(cls<<16) + gy*IMG + gx)*64 + ch*8;
            cp16(inH+d, srcH+so);
            cp16(inL+d, srcL+so);
        } else {
            *(uint4*)(inH+d) = make_uint4(0,0,0,0);
            *(uint4*)(inL+d) = make_uint4(0,0,0,0);
        }
    }
    asm volatile("cp.async.commit_group;");
    asm volatile("cp.async.wait_group 0;");
    __syncthreads();

    const int rl   = (lane&7) + ((lane>>3)&1)*8;
    const int ksel = (lane>>4)*16;
    const int px0 = mb*32 + rl, px1 = px0 + 16;
    const int pr0 = px0>>4, pc0 = px0&15, pr1 = px1>>4, pc1 = px1&15;
    const int kr   = (lane&7) + ((lane>>3)&1)*8;
    const int jsel = (lane>>4)&1;
    const unsigned boff0 = SWZ(kr*128 + (nb*4 + jsel)*16);
    const unsigned boff1 = SWZ(kr*128 + (nb*4 + 2 + jsel)*16);

    float osum[2][4][4];
#pragma unroll
    for (int a=0;a<2;a++)
#pragma unroll
        for (int b=0;b<4;b++)
#pragma unroll
            for (int j=0;j<4;j++) osum[a][b][j]=0.f;

    for (int sub=0; sub<nsub; sub++) {
        const int cs = cls*6 + sub0 + sub;
        const __nv_bfloat16* WH = g_wbh + (size_t)cs*9*4096;
        const __nv_bfloat16* WL = g_wbl + (size_t)cs*9*4096;
        auto stagew = [&](int buf, int st){
            for (int idx = tid; idx < 256; idx += 512) {
                int half = idx>>7, cc = idx&127, row = cc>>3, ch = cc&7;
                const __nv_bfloat16* sp = (half?WL:WH)
                    + ((size_t)(st>>2)*4096 + ((st&3)*16 + row)*64 + ch*8);
                cp16(wb + buf*4096 + half*2048 + SWZ(row*128 + ch*16), sp);
            }
        };
        float c[2][4][4];
#pragma unroll
        for (int a=0;a<2;a++)
#pragma unroll
            for (int b=0;b<4;b++)
#pragma unroll
                for (int j=0;j<4;j++) c[a][b][j]=0.f;
        stagew(0, 0);
        asm volatile("cp.async.commit_group;");
        for (int st=0; st<36; st++) {
            char* cw = wb + (st&1)*4096;
            if (st < 35) {
                stagew((st+1)&1, st+1);
                asm volatile("cp.async.commit_group;");
                asm volatile("cp.async.wait_group 1;");
            } else {
                asm volatile("cp.async.wait_group 0;");
            }
            __syncthreads();
            const int kyx = st>>2, icq = st&3;
            const int dy = kyx/3, dx = kyx - dy*3;
            const unsigned ao0 = SWZ(((pr0+dy)*18 + pc0+dx)*128 + icq*32 + ksel);
            const unsigned ao1 = SWZ(((pr1+dy)*18 + pc1+dx)*128 + icq*32 + ksel);
            unsigned ah0[4],al0[4],ah1[4],al1[4];
            ldmA(ah0, sptr(inH+ao0)); ldmA(al0, sptr(inL+ao0));
            ldmA(ah1, sptr(inH+ao1)); ldmA(al1, sptr(inL+ao1));
            unsigned bhA[4],bhB[4],blA[4],blB[4];
            ldmBT(bhA, sptr(cw+boff0));       ldmBT(bhB, sptr(cw+boff1));
            ldmBT(blA, sptr(cw+2048+boff0));  ldmBT(blB, sptr(cw+2048+boff1));
            const unsigned* BH[4] = { bhA, bhA+2, bhB, bhB+2 };
            const unsigned* BL[4] = { blA, blA+2, blB, blB+2 };
#pragma unroll
            for (int nt=0; nt<4; nt++) {
                mmabf(c[0][nt], ah0, BH[nt]);
                mmabf(c[0][nt], ah0, BL[nt]);
                mmabf(c[0][nt], al0, BH[nt]);
                mmabf(c[1][nt], ah1, BH[nt]);
                mmabf(c[1][nt], ah1, BL[nt]);
                mmabf(c[1][nt], al1, BH[nt]);
            }
            __syncthreads();
        }
        // BN + clip6 + accumulate
#pragma unroll
        for (int nt=0; nt<4; nt++) {
            int oc = nb*32 + nt*8 + (lane&3)*2;
            float s0 = S[(size_t)cs*64+oc], s1 = S[(size_t)cs*64+oc+1];
            float b0 = Bb[(size_t)cs*64+oc], b1 = Bb[(size_t)cs*64+oc+1];
#pragma unroll
            for (int mt=0; mt<2; mt++)
#pragma unroll
                for (int p=0; p<2; p++) {
                    osum[mt][nt][2*p]   += fminf(fmaxf(c[mt][nt][2*p]*s0+b0, 0.f), 6.f);
                    osum[mt][nt][2*p+1] += fminf(fmaxf(c[mt][nt][2*p+1]*s1+b1, 0.f), 6.f);
                }
        }
    }
    // write f32 (+ optional hi/lo channel-last)
#pragma unroll
    for (int mt=0; mt<2; mt++)
#pragma unroll
        for (int p=0; p<2; p++) {
            int pxl = mb*32 + mt*16 + (lane>>2) + p*8;
            int gp = (ty*16 + (pxl>>4))*IMG + tx*16 + (pxl&15);
#pragma unroll
            for (int nt=0; nt<4; nt++) {
                int oc = nb*32 + nt*8 + (lane&3)*2;
                float v0 = osum[mt][nt][2*p], v1 = osum[mt][nt][2*p+1];
                dstF[((size_t)(cls*64+oc))*HWPX + gp]   = v0;
                dstF[((size_t)(cls*64+oc+1))*HWPX + gp] = v1;
                if (dstH) {
                    size_t co = ((size_t)(cls<<16) + gp)*64 + oc;
                    __nv_bfloat16 h0=__float2bfloat16(v0), h1=__float2bfloat16(v1);
                    float l0 = v0-__bfloat162float(h0), l1 = v1-__bfloat162float(h1);
                    *(unsigned*)(dstH+co) = (unsigned)__bfloat16_as_ushort(h0)
                                          | ((unsigned)__bfloat16_as_ushort(h1)<<16);
                    *(unsigned*)(dstL+co) = packbf(l0, l1);
                }
            }
        }
}

// ---- cat 1x1 conv + BN + residual + relu -> d_out ----
__global__ __launch_bounds__(256)
void cat_k(const float* __restrict__ cw, const float* __restrict__ cs,
           const float* __restrict__ cb, float* __restrict__ out)
{
    __shared__ float ws[64*68];
    const int c = blockIdx.y, tid = threadIdx.x;
    const int ocg = tid>>5, pxg = tid&31;
    const int px = blockIdx.x*256 + pxg*8;
    ull acc[4][8];
#pragma unroll
    for (int p=0;p<4;p++)
#pragma unroll
        for (int j=0;j<8;j++) acc[p][j]=0ull;
    const float* srcs[3] = { g_x112 + (size_t)c*64*HWPX,
                             g_x223 + (size_t)c*64*HWPX,
                             g_x33  + (size_t)c*64*HWPX };
    for (int s=0; s<3; s++) {
        __syncthreads();
        for (int l=tid; l<4096; l+=256) {
            int oc=l>>6, ic=l&63;
            ws[ic*68+oc] = cw[(size_t)c*64*192 + oc*192 + s*64 + ic];
        }
        __syncthreads();
        const float* X = srcs[s] + px;
#pragma unroll 4
        for (int ic=0; ic<64; ic++) {
            float4 xa = *(const float4*)(X + (size_t)ic*HWPX);
            float4 xb = *(const float4*)(X + (size_t)ic*HWPX + 4);
            ull sv[8] = { splat2(xa.x),splat2(xa.y),splat2(xa.z),splat2(xa.w),
                          splat2(xb.x),splat2(xb.y),splat2(xb.z),splat2(xb.w) };
            const ull* wp = (const ull*)(ws + ic*68 + ocg*8);
            ull w0=wp[0],w1=wp[1],w2=wp[2],w3=wp[3];
#pragma unroll
            for (int j=0;j<8;j++) {
                acc[0][j]=ffma2(w0,sv[j],acc[0][j]); acc[1][j]=ffma2(w1,sv[j],acc[1][j]);
                acc[2][j]=ffma2(w2,sv[j],acc[2][j]); acc[3][j]=ffma2(w3,sv[j],acc[3][j]);
            }
        }
    }
    const float* Sc = cs + (size_t)c*64 + ocg*8;
    const float* Bc = cb + (size_t)c*64 + ocg*8;
    const float* XO = g_xo + (size_t)c*64*HWPX + px;
    float* O = out + (size_t)c*64*HWPX + px;
#pragma unroll
    for (int p=0;p<4;p++) {
        float s0=Sc[2*p],s1=Sc[2*p+1],b0=Bc[2*p],b1=Bc[2*p+1];
#pragma unroll
        for (int j=0;j<8;j++) {
            float2 v = unpk(acc[p][j]);
            size_t o0 = (size_t)(ocg*8+2*p)*HWPX + j;
            size_t o1 = (size_t)(ocg*8+2*p+1)*HWPX + j;
            O[o0] = fmaxf(v.x*s0+b0 + XO[o0], 0.f);
            O[o1] = fmaxf(v.y*s1+b1 + XO[o1], 0.f);
        }
    }
}

extern "C" void kernel_launch(void* const* d_in, const int* in_sizes, int n_in,
                              void* d_out, int out_size)
{
    const float* x    = (const float*)d_in[0];
    const float* qkw  = (const float*)d_in[1];
    const float* qks  = (const float*)d_in[2];
    const float* qkb  = (const float*)d_in[3];
    const float* relb = (const float*)d_in[4];
    const float* wvw  = (const float*)d_in[5];
    const float* wvs  = (const float*)d_in[6];
    const float* wvb  = (const float*)d_in[7];
    const float* mmsw = (const float*)d_in[8];
    const float* mmss = (const float*)d_in[9];
    const float* mmsb = (const float*)d_in[10];
    const float* catw = (const float*)d_in[11];
    const float* cats = (const float*)d_in[12];
    const float* catb = (const float*)d_in[13];
    float* out = (float*)d_out;

    float *qk, *v, *xo, *a112, *b223, *c33;
    cudaGetSymbolAddress((void**)&qk,   g_qk);
    cudaGetSymbolAddress((void**)&v,    g_v);
    cudaGetSymbolAddress((void**)&xo,   g_xo);
    cudaGetSymbolAddress((void**)&a112, g_x112);
    cudaGetSymbolAddress((void**)&b223, g_x223);
    cudaGetSymbolAddress((void**)&c33,  g_x33);
    __nv_bfloat16 *h0,*l0,*h1,*l1,*h2,*l2;
    cudaGetSymbolAddress((void**)&h0, g_h0); cudaGetSymbolAddress((void**)&l0, g_l0);
    cudaGetSymbolAddress((void**)&h1, g_h1); cudaGetSymbolAddress((void**)&l1, g_l1);
    cudaGetSymbolAddress((void**)&h2, g_h2); cudaGetSymbolAddress((void**)&l2, g_l2);

    cudaFuncSetAttribute(c3mma_k, cudaFuncAttributeMaxDynamicSharedMemorySize, C3_SMEMB);

    conv1x1_k<128><<<dim3(512, NCLS), 256>>>(x, qkw, qks, qkb, qk);
    conv1x1_k<64> <<<dim3(256, NCLS), 256>>>(x, wvw, wvs, wvb, v);
    rbar_k<<<NCLS, 64>>>(relb);
    mask_k<<<dim3(1024, NCLS), 64>>>();
    good_k<<<256, 256>>>();
    attn_k<<<dim3(1024, NCLS), 256>>>(x, relb, xo);
    wprep_k<<<(36*9*64*64 + 255)/256, 256>>>(mmsw);
    c3mma_k<<<dim3(16, 16, NCLS), 512, C3_SMEMB>>>(h0, l0, mmss, mmsb, a112, h1, l1, 3, 0);
    c3mma_k<<<dim3(16, 16, NCLS), 512, C3_SMEMB>>>(h1, l1, mmss, mmsb, b223, h2, l2, 2, 3);
    c3mma_k<<<dim3(16, 16, NCLS), 512, C3_SMEMB>>>(h2, l2, mmss, mmsb, c33, (__nv_bfloat16*)0, (__nv_bfloat16*)0, 1, 5);
    cat_k<<<dim3(256, NCLS), 256>>>(catw, cats, catb, out);
}

// round 11
// speedup vs baseline: 1.5631x; 1.0989x over previous
#include <cuda_runtime.h>
#include <cuda_bf16.h>

typedef unsigned long long ull;
#define HWPX 65536
#define IMG  256
#define NCLS 6
#define SWZ(o) ((unsigned)(o) ^ ((((unsigned)(o))>>3)&0x70))

// ---- scratch ----
__device__ float g_qk  [(size_t)NCLS*128*HWPX];
__device__ float g_v   [(size_t)NCLS*64*HWPX];
__device__ float g_xo  [(size_t)NCLS*64*HWPX];
__device__ float g_x112[(size_t)NCLS*64*HWPX];
__device__ float g_x223[(size_t)NCLS*64*HWPX];
__device__ float g_x33 [(size_t)NCLS*64*HWPX];
__device__ float g_mask[(size_t)NCLS*65536];
__device__ float g_good[(size_t)NCLS*65536];
__device__ float g_rbar[NCLS*64];
// channel-last bf16 hi/lo activations: [cls][px(65536)][ic(64)]
__device__ __nv_bfloat16 g_h0[(size_t)NCLS*HWPX*64], g_l0[(size_t)NCLS*HWPX*64];
__device__ __nv_bfloat16 g_h1[(size_t)NCLS*HWPX*64], g_l1[(size_t)NCLS*HWPX*64];
__device__ __nv_bfloat16 g_h2[(size_t)NCLS*HWPX*64], g_l2[(size_t)NCLS*HWPX*64];
// conv weights bf16 hi/lo: [cs(36)][kyx(9)][ic(64)][oc(64)]
__device__ __nv_bfloat16 g_wbh[(size_t)36*9*64*64], g_wbl[(size_t)36*9*64*64];

__device__ __forceinline__ ull ffma2(ull a, ull b, ull c){
    ull d; asm("fma.rn.f32x2 %0, %1, %2, %3;" : "=l"(d) : "l"(a), "l"(b), "l"(c)); return d;
}
__device__ __forceinline__ ull splat2(float v){
    ull d; unsigned u = __float_as_uint(v);
    asm("mov.b64 %0, {%1, %1};" : "=l"(d) : "r"(u)); return d;
}
__device__ __forceinline__ float2 unpk(ull a){
    unsigned lo, hi; asm("mov.b64 {%0, %1}, %2;" : "=r"(lo), "=r"(hi) : "l"(a));
    return make_float2(__uint_as_float(lo), __uint_as_float(hi));
}
__device__ __forceinline__ void cp16(void* smem_dst, const void* gsrc){
    unsigned d = (unsigned)__cvta_generic_to_shared(smem_dst);
    asm volatile("cp.async.ca.shared.global [%0], [%1], 16;" :: "r"(d), "l"(gsrc));
}
__device__ __forceinline__ unsigned sptr(const void* p){ return (unsigned)__cvta_generic_to_shared(p); }
__device__ __forceinline__ void ldmA(unsigned* r, unsigned a){
    asm volatile("ldmatrix.sync.aligned.m8n8.x4.shared.b16 {%0,%1,%2,%3},[%4];"
        :"=r"(r[0]),"=r"(r[1]),"=r"(r[2]),"=r"(r[3]):"r"(a));
}
__device__ __forceinline__ void ldmBT(unsigned* r, unsigned a){
    asm volatile("ldmatrix.sync.aligned.m8n8.x4.trans.shared.b16 {%0,%1,%2,%3},[%4];"
        :"=r"(r[0]),"=r"(r[1]),"=r"(r[2]),"=r"(r[3]):"r"(a));
}
__device__ __forceinline__ void mmabf(float* c, const unsigned* a, const unsigned* b){
    asm volatile("mma.sync.aligned.m16n8k16.row.col.f32.bf16.bf16.f32 "
        "{%0,%1,%2,%3},{%4,%5,%6,%7},{%8,%9},{%0,%1,%2,%3};"
        :"+f"(c[0]),"+f"(c[1]),"+f"(c[2]),"+f"(c[3])
        :"r"(a[0]),"r"(a[1]),"r"(a[2]),"r"(a[3]),"r"(b[0]),"r"(b[1]));
}
__device__ __forceinline__ unsigned packbf(float a, float b){
    __nv_bfloat16 ha=__float2bfloat16(a), hb=__float2bfloat16(b);
    return (unsigned)__bfloat16_as_ushort(ha) | ((unsigned)__bfloat16_as_ushort(hb)<<16);
}

// ---- 1x1 conv + BN + ReLU ----
template<int OC>
__global__ __launch_bounds__(256)
void conv1x1_k(const float* __restrict__ x, const float* __restrict__ W,
               const float* __restrict__ S, const float* __restrict__ Bb,
               float* __restrict__ out)
{
    constexpr int P = OC + 4, OCG = OC/8, PXG = 256/OCG;
    __shared__ float ws[64*P];
    const int c = blockIdx.y;
    const float* Wc = W + (size_t)c*OC*64;
    for (int l = threadIdx.x; l < 64*OC; l += 256) {
        int oc = l>>6, ic = l&63; ws[ic*P+oc] = Wc[(size_t)oc*64+ic];
    }
    __syncthreads();
    const int ocg = threadIdx.x / PXG, pxg = threadIdx.x % PXG;
    const int px = blockIdx.x*(PXG*8) + pxg*8;
    const float* X = x + (size_t)c*64*HWPX + px;
    ull acc[4][8];
#pragma unroll
    for (int p=0;p<4;p++)
#pragma unroll
        for (int j=0;j<8;j++) acc[p][j]=0ull;
#pragma unroll 4
    for (int ic=0; ic<64; ic++) {
        float4 xa = *(const float4*)(X + (size_t)ic*HWPX);
        float4 xb = *(const float4*)(X + (size_t)ic*HWPX + 4);
        ull sv[8] = { splat2(xa.x),splat2(xa.y),splat2(xa.z),splat2(xa.w),
                      splat2(xb.x),splat2(xb.y),splat2(xb.z),splat2(xb.w) };
        const ull* wp = (const ull*)(ws + ic*P + ocg*8);
        ull w0=wp[0],w1=wp[1],w2=wp[2],w3=wp[3];
#pragma unroll
        for (int j=0;j<8;j++) {
            acc[0][j]=ffma2(w0,sv[j],acc[0][j]); acc[1][j]=ffma2(w1,sv[j],acc[1][j]);
            acc[2][j]=ffma2(w2,sv[j],acc[2][j]); acc[3][j]=ffma2(w3,sv[j],acc[3][j]);
        }
    }
    const float* Sc = S + (size_t)c*OC + ocg*8;
    const float* Bc = Bb + (size_t)c*OC + ocg*8;
    float* O = out + (size_t)c*OC*HWPX + px;
#pragma unroll
    for (int p=0;p<4;p++) {
        float s0=Sc[2*p],s1=Sc[2*p+1],b0=Bc[2*p],b1=Bc[2*p+1];
        float r0[8],r1[8];
#pragma unroll
        for (int j=0;j<8;j++) {
            float2 v = unpk(acc[p][j]);
            r0[j]=fmaxf(v.x*s0+b0,0.f); r1[j]=fmaxf(v.y*s1+b1,0.f);
        }
        float* O0 = O + (size_t)(ocg*8+2*p)*HWPX;
        float* O1 = O + (size_t)(ocg*8+2*p+1)*HWPX;
        *(float4*)O0     = make_float4(r0[0],r0[1],r0[2],r0[3]);
        *(float4*)(O0+4) = make_float4(r0[4],r0[5],r0[6],r0[7]);
        *(float4*)O1     = make_float4(r1[0],r1[1],r1[2],r1[3]);
        *(float4*)(O1+4) = make_float4(r1[4],r1[5],r1[6],r1[7]);
    }
}

__global__ void rbar_k(const float* __restrict__ relb)
{
    int idx = blockIdx.x*64 + threadIdx.x;
    if (idx >= NCLS*64) return;
    int c = idx>>6, k = idx&63, ky = k>>3, kx = k&7;
    float s = 0.f;
    for (int q=0;q<64;q++) {
        int qy=q>>3, qx=q&7;
        const float* p = relb + (size_t)c*900 + ((qy-ky+7)*15 + (qx-kx+7))*4;
        s += p[0]+p[1]+p[2]+p[3];
    }
    g_rbar[idx] = s * (1.f/256.f);
}

__global__ void mask_k()
{
    __shared__ float qw[64*65], kw[64*65], qs[64];
    const int c = blockIdx.y, n = blockIdx.x;
    const int wy = n>>5, wx = n&31, t = threadIdx.x;
    const int px = (wy*8 + (t>>3))*IMG + wx*8 + (t&7);
    const float* Q = g_qk + (size_t)c*128*HWPX;
    for (int ch=0; ch<64; ch++) {
        qw[ch*65+t] = Q[(size_t)ch*HWPX + px];
        kw[ch*65+t] = Q[(size_t)(64+ch)*HWPX + px];
    }
    __syncthreads();
    float s = 0.f;
    for (int q=0;q<64;q++) s += qw[t*65+q];
    qs[t] = s;
    __syncthreads();
    float m = 0.f;
    for (int ch=0;ch<64;ch++) m += qs[ch]*kw[ch*65+t];
    g_mask[(size_t)c*65536 + n*64 + t] = m*(0.25f/256.f) + g_rbar[c*64+t];
}

__global__ void good_k()
{
    int idx = blockIdx.x*256 + threadIdx.x;
    float m[NCLS], mx = -1e30f;
#pragma unroll
    for (int c=0;c<NCLS;c++) { m[c]=g_mask[(size_t)c*65536+idx]; mx=fmaxf(mx,m[c]); }
#pragma unroll
    for (int c=0;c<NCLS;c++) g_good[(size_t)c*65536+idx] = (m[c]==mx)?1.f:-1.f;
}

__global__ __launch_bounds__(256)
void attn_k(const float* __restrict__ x, const float* __restrict__ relb,
            float* __restrict__ xo)
{
    __shared__ float buf[4*64*16];
    __shared__ float rel_s[900];
    __shared__ float gg[64];
    const int c = blockIdx.y, n = blockIdx.x;
    const int wy = n>>5, wx = n&31, tid = threadIdx.x;
    for (int l=tid; l<900; l+=256) rel_s[l] = relb[(size_t)c*900+l];
    if (tid < 64) gg[tid] = g_good[(size_t)c*65536 + n*64 + tid];
    const float* Q = g_qk + (size_t)c*128*HWPX;
    for (int l=tid; l<4096; l+=256) {
        int pos=l&63, ch=l>>6;
        int gpx = (wy*8+(pos>>3))*IMG + wx*8 + (pos&7);
        buf[((ch>>4)*64+pos)*16 + (ch&15)] = Q[(size_t)ch*HWPX + gpx];
    }
    __syncthreads();
    const int h = tid>>6, q = tid&63;
    float qv[16];
#pragma unroll
    for (int d=0;d<16;d++) qv[d] = buf[(h*64+q)*16+d];
    __syncthreads();
    for (int l=tid; l<4096; l+=256) {
        int pos=l&63, ch=l>>6;
        int gpx = (wy*8+(pos>>3))*IMG + wx*8 + (pos&7);
        buf[((ch>>4)*64+pos)*16 + (ch&15)] = Q[(size_t)(64+ch)*HWPX + gpx];
    }
    __syncthreads();
    float dt[64];
    const int qy=q>>3, qx=q&7;
#pragma unroll
    for (int k=0;k<64;k++) {
        const float4* kp = (const float4*)(buf + (h*64+k)*16);
        float4 k0=kp[0],k1=kp[1],k2=kp[2],k3=kp[3];
        float a = qv[0]*k0.x+qv[1]*k0.y+qv[2]*k0.z+qv[3]*k0.w
                + qv[4]*k1.x+qv[5]*k1.y+qv[6]*k1.z+qv[7]*k1.w
                + qv[8]*k2.x+qv[9]*k2.y+qv[10]*k2.z+qv[11]*k2.w
                + qv[12]*k3.x+qv[13]*k3.y+qv[14]*k3.z+qv[15]*k3.w;
        int ky=k>>3, kx=k&7;
        dt[k] = a*0.25f + rel_s[((qy-ky+7)*15+(qx-kx+7))*4 + h];
    }
    float mx = -1e30f;
#pragma unroll
    for (int k=0;k<64;k++) mx = fmaxf(mx, dt[k]);
    float sum = 0.f;
#pragma unroll
    for (int k=0;k<64;k++) { dt[k]=__expf(dt[k]-mx); sum+=dt[k]; }
    float sc = gg[q]/sum;
#pragma unroll
    for (int k=0;k<64;k++) dt[k] *= sc*gg[k];
    __syncthreads();
    const float* V = g_v + (size_t)c*64*HWPX;
    for (int l=tid; l<4096; l+=256) {
        int pos=l&63, ch=l>>6;
        int gpx = (wy*8+(pos>>3))*IMG + wx*8 + (pos&7);
        buf[((ch>>4)*64+pos)*16 + (ch&15)] = V[(size_t)ch*HWPX + gpx];
    }
    __syncthreads();
    float o[16];
#pragma unroll
    for (int d=0;d<16;d++) o[d]=0.f;
#pragma unroll
    for (int k=0;k<64;k++) {
        float a = dt[k];
        const float4* vp = (const float4*)(buf + (h*64+k)*16);
        float4 v0=vp[0],v1=vp[1],v2=vp[2],v3=vp[3];
        o[0]+=a*v0.x; o[1]+=a*v0.y; o[2]+=a*v0.z; o[3]+=a*v0.w;
        o[4]+=a*v1.x; o[5]+=a*v1.y; o[6]+=a*v1.z; o[7]+=a*v1.w;
        o[8]+=a*v2.x; o[9]+=a*v2.y; o[10]+=a*v2.z; o[11]+=a*v2.w;
        o[12]+=a*v3.x; o[13]+=a*v3.y; o[14]+=a*v3.z; o[15]+=a*v3.w;
    }
    const int gpx = (wy*8+qy)*IMG + wx*8 + qx;
    const float* X = x + (size_t)c*64*HWPX;
    float* O = xo + (size_t)c*64*HWPX;
    float r[16];
#pragma unroll
    for (int d=0;d<16;d++) {
        size_t off = (size_t)(h*16+d)*HWPX + gpx;
        r[d] = X[off] + o[d];
        O[off] = r[d];
    }
    unsigned ph[8], pl[8];
#pragma unroll
    for (int d=0;d<8;d++) {
        float a = r[2*d], b = r[2*d+1];
        __nv_bfloat16 ha=__float2bfloat16(a), hb=__float2bfloat16(b);
        float la = a - __bfloat162float(ha), lb = b - __bfloat162float(hb);
        ph[d] = (unsigned)__bfloat16_as_ushort(ha) | ((unsigned)__bfloat16_as_ushort(hb)<<16);
        pl[d] = packbf(la, lb);
    }
    size_t co = ((size_t)(c<<16) + gpx)*64 + h*16;
    *(uint4*)(g_h0+co)   = make_uint4(ph[0],ph[1],ph[2],ph[3]);
    *(uint4*)(g_h0+co+8) = make_uint4(ph[4],ph[5],ph[6],ph[7]);
    *(uint4*)(g_l0+co)   = make_uint4(pl[0],pl[1],pl[2],pl[3]);
    *(uint4*)(g_l0+co+8) = make_uint4(pl[4],pl[5],pl[6],pl[7]);
}

// ---- weight prep: f32 [cs][oc][ic][3][3] -> bf16 hi/lo [cs][kyx][ic][oc] ----
__global__ void wprep_k(const float* __restrict__ W)
{
    int i = blockIdx.x*256 + threadIdx.x;
    if (i >= 36*9*64*64) return;
    int kyx = i % 9; int t = i / 9;
    int ic = t & 63; t >>= 6;
    int oc = t & 63; int cs = t >> 6;
    float w = W[(((size_t)cs*64 + oc)*64 + ic)*9 + kyx];
    __nv_bfloat16 h = __float2bfloat16(w);
    float l = w - __bfloat162float(h);
    size_t d = ((size_t)cs*9 + kyx)*4096 + ic*64 + oc;
    g_wbh[d] = h; g_wbl[d] = __float2bfloat16(l);
}

// ---- conv3x3 via bf16 mma 3-pass split; K=64 stages (one per kyx) ----
#define C3_HALF 41984
#define WSTG    16384
#define C3_SMEMB (2*C3_HALF + 2*WSTG)   // 116736
__global__ __launch_bounds__(512,1)
void c3mma_k(const __nv_bfloat16* __restrict__ srcH, const __nv_bfloat16* __restrict__ srcL,
             const float* __restrict__ S, const float* __restrict__ Bb,
             float* __restrict__ dstF, __nv_bfloat16* __restrict__ dstH,
             __nv_bfloat16* __restrict__ dstL, int nsub, int sub0)
{
    extern __shared__ char sm[];
    char* inH = sm; char* inL = sm + C3_HALF;
    char* wb  = sm + 2*C3_HALF;                 // [buf2][WSTG: hi 8KB + lo 8KB]
    const int cls = blockIdx.z, ty = blockIdx.y, tx = blockIdx.x;
    const int tid = threadIdx.x, lane = tid&31, wid = tid>>5;
    const int mb = wid&7, nb = wid>>3;

    // stage halo 18x18 px x 64ic (swizzled rows of 128B)
    for (int idx = tid; idx < 324*8; idx += 512) {
        int p = idx>>3, ch = idx&7;
        int gy = ty*16 - 1 + p/18, gx = tx*16 - 1 + p%18;
        unsigned d = SWZ(p*128 + ch*16);
        if ((unsigned)gy<256u && (unsigned)gx<256u) {
            size_t so = ((size_t)(cls<<16) + gy*IMG + gx)*64 + ch*8;
            cp16(inH+d, srcH+so);
            cp16(inL+d, srcL+so);
        } else {
            *(uint4*)(inH+d) = make_uint4(0,0,0,0);
            *(uint4*)(inL+d) = make_uint4(0,0,0,0);
        }
    }
    asm volatile("cp.async.commit_group;");
    asm volatile("cp.async.wait_group 0;");
    __syncthreads();

    const int rl   = (lane&7) + ((lane>>3)&1)*8;
    const int ksel = (lane>>4)*16;
    const int px0 = mb*32 + rl, px1 = px0 + 16;
    const int pr0 = px0>>4, pc0 = px0&15, pr1 = px1>>4, pc1 = px1&15;
    const int kr   = (lane&7) + ((lane>>3)&1)*8;
    const int jsel = (lane>>4)&1;

    float osum[2][4][4];
#pragma unroll
    for (int a=0;a<2;a++)
#pragma unroll
        for (int b=0;b<4;b++)
#pragma unroll
            for (int j=0;j<4;j++) osum[a][b][j]=0.f;

    for (int sub=0; sub<nsub; sub++) {
        const int cs = cls*6 + sub0 + sub;
        const __nv_bfloat16* WH = g_wbh + (size_t)cs*9*4096;
        const __nv_bfloat16* WL = g_wbl + (size_t)cs*9*4096;
        // stage one kyx: 64ic x 64oc hi (8KB) + lo (8KB)
        auto stagew = [&](int buf, int kyx){
#pragma unroll
            for (int t=0;t<2;t++){
                int idx = tid + t*512;
                int half = idx>>9, r = (idx>>3)&63, ch = idx&7;
                const __nv_bfloat16* sp = (half?WL:WH) + (size_t)kyx*4096 + r*64 + ch*8;
                cp16(wb + buf*WSTG + half*8192 + SWZ(r*128+ch*16), sp);
            }
        };
        float c[2][4][4];
#pragma unroll
        for (int a=0;a<2;a++)
#pragma unroll
            for (int b=0;b<4;b++)
#pragma unroll
                for (int j=0;j<4;j++) c[a][b][j]=0.f;
        stagew(0, 0);
        asm volatile("cp.async.commit_group;");
        for (int st=0; st<9; st++) {
            char* cw = wb + (st&1)*WSTG;
            if (st < 8) {
                stagew((st+1)&1, st+1);
                asm volatile("cp.async.commit_group;");
                asm volatile("cp.async.wait_group 1;");
            } else {
                asm volatile("cp.async.wait_group 0;");
            }
            __syncthreads();
            const int dy = st/3, dx = st - dy*3;
#pragma unroll
            for (int kc=0; kc<4; kc++) {
                const unsigned ao0 = SWZ(((pr0+dy)*18 + pc0+dx)*128 + kc*32 + ksel);
                const unsigned ao1 = SWZ(((pr1+dy)*18 + pc1+dx)*128 + kc*32 + ksel);
                unsigned ah0[4],al0[4],ah1[4],al1[4];
                ldmA(ah0, sptr(inH+ao0)); ldmA(al0, sptr(inL+ao0));
                ldmA(ah1, sptr(inH+ao1)); ldmA(al1, sptr(inL+ao1));
                const unsigned bo0 = SWZ((kc*16+kr)*128 + (nb*4 + jsel)*16);
                const unsigned bo1 = SWZ((kc*16+kr)*128 + (nb*4 + 2 + jsel)*16);
                unsigned bhA[4],bhB[4],blA[4],blB[4];
                ldmBT(bhA, sptr(cw+bo0));       ldmBT(bhB, sptr(cw+bo1));
                ldmBT(blA, sptr(cw+8192+bo0));  ldmBT(blB, sptr(cw+8192+bo1));
                const unsigned* BH[4] = { bhA, bhA+2, bhB, bhB+2 };
                const unsigned* BL[4] = { blA, blA+2, blB, blB+2 };
#pragma unroll
                for (int nt=0; nt<4; nt++) {
                    mmabf(c[0][nt], ah0, BH[nt]);
                    mmabf(c[0][nt], ah0, BL[nt]);
                    mmabf(c[0][nt], al0, BH[nt]);
                    mmabf(c[1][nt], ah1, BH[nt]);
                    mmabf(c[1][nt], ah1, BL[nt]);
                    mmabf(c[1][nt], al1, BH[nt]);
                }
            }
            __syncthreads();
        }
        // BN + clip6 + accumulate
#pragma unroll
        for (int nt=0; nt<4; nt++) {
            int oc = nb*32 + nt*8 + (lane&3)*2;
            float s0 = S[(size_t)cs*64+oc], s1 = S[(size_t)cs*64+oc+1];
            float b0 = Bb[(size_t)cs*64+oc], b1 = Bb[(size_t)cs*64+oc+1];
#pragma unroll
            for (int mt=0; mt<2; mt++)
#pragma unroll
                for (int p=0; p<2; p++) {
                    osum[mt][nt][2*p]   += fminf(fmaxf(c[mt][nt][2*p]*s0+b0, 0.f), 6.f);
                    osum[mt][nt][2*p+1] += fminf(fmaxf(c[mt][nt][2*p+1]*s1+b1, 0.f), 6.f);
                }
        }
    }
    // write f32 (+ optional hi/lo channel-last)
#pragma unroll
    for (int mt=0; mt<2; mt++)
#pragma unroll
        for (int p=0; p<2; p++) {
            int pxl = mb*32 + mt*16 + (lane>>2) + p*8;
            int gp = (ty*16 + (pxl>>4))*IMG + tx*16 + (pxl&15);
#pragma unroll
            for (int nt=0; nt<4; nt++) {
                int oc = nb*32 + nt*8 + (lane&3)*2;
                float v0 = osum[mt][nt][2*p], v1 = osum[mt][nt][2*p+1];
                dstF[((size_t)(cls*64+oc))*HWPX + gp]   = v0;
                dstF[((size_t)(cls*64+oc+1))*HWPX + gp] = v1;
                if (dstH) {
                    size_t co = ((size_t)(cls<<16) + gp)*64 + oc;
                    __nv_bfloat16 h0=__float2bfloat16(v0), h1=__float2bfloat16(v1);
                    float l0 = v0-__bfloat162float(h0), l1 = v1-__bfloat162float(h1);
                    *(unsigned*)(dstH+co) = (unsigned)__bfloat16_as_ushort(h0)
                                          | ((unsigned)__bfloat16_as_ushort(h1)<<16);
                    *(unsigned*)(dstL+co) = packbf(l0, l1);
                }
            }
        }
}

// ---- cat 1x1 conv + BN + residual + relu -> d_out ----
__global__ __launch_bounds__(256)
void cat_k(const float* __restrict__ cw, const float* __restrict__ cs,
           const float* __restrict__ cb, float* __restrict__ out)
{
    __shared__ float ws[64*68];
    const int c = blockIdx.y, tid = threadIdx.x;
    const int ocg = tid>>5, pxg = tid&31;
    const int px = blockIdx.x*256 + pxg*8;
    ull acc[4][8];
#pragma unroll
    for (int p=0;p<4;p++)
#pragma unroll
        for (int j=0;j<8;j++) acc[p][j]=0ull;
    const float* srcs[3] = { g_x112 + (size_t)c*64*HWPX,
                             g_x223 + (size_t)c*64*HWPX,
                             g_x33  + (size_t)c*64*HWPX };
    for (int s=0; s<3; s++) {
        __syncthreads();
        for (int l=tid; l<4096; l+=256) {
            int oc=l>>6, ic=l&63;
            ws[ic*68+oc] = cw[(size_t)c*64*192 + oc*192 + s*64 + ic];
        }
        __syncthreads();
        const float* X = srcs[s] + px;
#pragma unroll 4
        for (int ic=0; ic<64; ic++) {
            float4 xa = *(const float4*)(X + (size_t)ic*HWPX);
            float4 xb = *(const float4*)(X + (size_t)ic*HWPX + 4);
            ull sv[8] = { splat2(xa.x),splat2(xa.y),splat2(xa.z),splat2(xa.w),
                          splat2(xb.x),splat2(xb.y),splat2(xb.z),splat2(xb.w) };
            const ull* wp = (const ull*)(ws + ic*68 + ocg*8);
            ull w0=wp[0],w1=wp[1],w2=wp[2],w3=wp[3];
#pragma unroll
            for (int j=0;j<8;j++) {
                acc[0][j]=ffma2(w0,sv[j],acc[0][j]); acc[1][j]=ffma2(w1,sv[j],acc[1][j]);
                acc[2][j]=ffma2(w2,sv[j],acc[2][j]); acc[3][j]=ffma2(w3,sv[j],acc[3][j]);
            }
        }
    }
    const float* Sc = cs + (size_t)c*64 + ocg*8;
    const float* Bc = cb + (size_t)c*64 + ocg*8;
    const float* XO = g_xo + (size_t)c*64*HWPX + px;
    float* O = out + (size_t)c*64*HWPX + px;
#pragma unroll
    for (int p=0;p<4;p++) {
        float s0=Sc[2*p],s1=Sc[2*p+1],b0=Bc[2*p],b1=Bc[2*p+1];
#pragma unroll
        for (int j=0;j<8;j++) {
            float2 v = unpk(acc[p][j]);
            size_t o0 = (size_t)(ocg*8+2*p)*HWPX + j;
            size_t o1 = (size_t)(ocg*8+2*p+1)*HWPX + j;
            O[o0] = fmaxf(v.x*s0+b0 + XO[o0], 0.f);
            O[o1] = fmaxf(v.y*s1+b1 + XO[o1], 0.f);
        }
    }
}

extern "C" void kernel_launch(void* const* d_in, const int* in_sizes, int n_in,
                              void* d_out, int out_size)
{
    const float* x    = (const float*)d_in[0];
    const float* qkw  = (const float*)d_in[1];
    const float* qks  = (const float*)d_in[2];
    const float* qkb  = (const float*)d_in[3];
    const float* relb = (const float*)d_in[4];
    const float* wvw  = (const float*)d_in[5];
    const float* wvs  = (const float*)d_in[6];
    const float* wvb  = (const float*)d_in[7];
    const float* mmsw = (const float*)d_in[8];
    const float* mmss = (const float*)d_in[9];
    const float* mmsb = (const float*)d_in[10];
    const float* catw = (const float*)d_in[11];
    const float* cats = (const float*)d_in[12];
    const float* catb = (const float*)d_in[13];
    float* out = (float*)d_out;

    float *qk, *v, *xo, *a112, *b223, *c33;
    cudaGetSymbolAddress((void**)&qk,   g_qk);
    cudaGetSymbolAddress((void**)&v,    g_v);
    cudaGetSymbolAddress((void**)&xo,   g_xo);
    cudaGetSymbolAddress((void**)&a112, g_x112);
    cudaGetSymbolAddress((void**)&b223, g_x223);
    cudaGetSymbolAddress((void**)&c33,  g_x33);
    __nv_bfloat16 *h0,*l0,*h1,*l1,*h2,*l2;
    cudaGetSymbolAddress((void**)&h0, g_h0); cudaGetSymbolAddress((void**)&l0, g_l0);
    cudaGetSymbolAddress((void**)&h1, g_h1); cudaGetSymbolAddress((void**)&l1, g_l1);
    cudaGetSymbolAddress((void**)&h2, g_h2); cudaGetSymbolAddress((void**)&l2, g_l2);

    cudaFuncSetAttribute(c3mma_k, cudaFuncAttributeMaxDynamicSharedMemorySize, C3_SMEMB);

    conv1x1_k<128><<<dim3(512, NCLS), 256>>>(x, qkw, qks, qkb, qk);
    conv1x1_k<64> <<<dim3(256, NCLS), 256>>>(x, wvw, wvs, wvb, v);
    rbar_k<<<NCLS, 64>>>(relb);
    mask_k<<<dim3(1024, NCLS), 64>>>();
    good_k<<<256, 256>>>();
    attn_k<<<dim3(1024, NCLS), 256>>>(x, relb, xo);
    wprep_k<<<(36*9*64*64 + 255)/256, 256>>>(mmsw);
    c3mma_k<<<dim3(16, 16, NCLS), 512, C3_SMEMB>>>(h0, l0, mmss, mmsb, a112, h1, l1, 3, 0);
    c3mma_k<<<dim3(16, 16, NCLS), 512, C3_SMEMB>>>(h1, l1, mmss, mmsb, b223, h2, l2, 2, 3);
    c3mma_k<<<dim3(16, 16, NCLS), 512, C3_SMEMB>>>(h2, l2, mmss, mmsb, c33, (__nv_bfloat16*)0, (__nv_bfloat16*)0, 1, 5);
    cat_k<<<dim3(256, NCLS), 256>>>(catw, cats, catb, out);
}

// round 14
// speedup vs baseline: 1.5815x; 1.0118x over previous
#include <cuda_runtime.h>
#include <cuda_bf16.h>

typedef unsigned long long ull;
#define HWPX 65536
#define IMG  256
#define NCLS 6
#define SWZ(o) ((unsigned)(o) ^ ((((unsigned)(o))>>3)&0x70))

// ---- scratch ----
__device__ float g_qk  [(size_t)NCLS*128*HWPX];
__device__ float g_v   [(size_t)NCLS*64*HWPX];
__device__ float g_xo  [(size_t)NCLS*64*HWPX];
__device__ float g_x112[(size_t)NCLS*64*HWPX];
__device__ float g_x223[(size_t)NCLS*64*HWPX];
__device__ float g_x33 [(size_t)NCLS*64*HWPX];
__device__ float g_mask[(size_t)NCLS*65536];
__device__ float g_good[(size_t)NCLS*65536];
__device__ float g_rbar[NCLS*64];
// channel-last bf16 hi/lo activations: [cls][px(65536)][ic(64)]
__device__ __nv_bfloat16 g_h0[(size_t)NCLS*HWPX*64], g_l0[(size_t)NCLS*HWPX*64];
__device__ __nv_bfloat16 g_h1[(size_t)NCLS*HWPX*64], g_l1[(size_t)NCLS*HWPX*64];
__device__ __nv_bfloat16 g_h2[(size_t)NCLS*HWPX*64], g_l2[(size_t)NCLS*HWPX*64];
// conv weights bf16 hi/lo: [cs(36)][kyx(9)][ic(64)][oc(64)]
__device__ __nv_bfloat16 g_wbh[(size_t)36*9*64*64], g_wbl[(size_t)36*9*64*64];

__device__ __forceinline__ ull ffma2(ull a, ull b, ull c){
    ull d; asm("fma.rn.f32x2 %0, %1, %2, %3;" : "=l"(d) : "l"(a), "l"(b), "l"(c)); return d;
}
__device__ __forceinline__ ull splat2(float v){
    ull d; unsigned u = __float_as_uint(v);
    asm("mov.b64 %0, {%1, %1};" : "=l"(d) : "r"(u)); return d;
}
__device__ __forceinline__ float2 unpk(ull a){
    unsigned lo, hi; asm("mov.b64 {%0, %1}, %2;" : "=r"(lo), "=r"(hi) : "l"(a));
    return make_float2(__uint_as_float(lo), __uint_as_float(hi));
}
__device__ __forceinline__ void cp16(void* smem_dst, const void* gsrc){
    unsigned d = (unsigned)__cvta_generic_to_shared(smem_dst);
    asm volatile("cp.async.ca.shared.global [%0], [%1], 16;" :: "r"(d), "l"(gsrc));
}
__device__ __forceinline__ unsigned sptr(const void* p){ return (unsigned)__cvta_generic_to_shared(p); }
__device__ __forceinline__ void ldmA(unsigned* r, unsigned a){
    asm volatile("ldmatrix.sync.aligned.m8n8.x4.shared.b16 {%0,%1,%2,%3},[%4];"
        :"=r"(r[0]),"=r"(r[1]),"=r"(r[2]),"=r"(r[3]):"r"(a));
}
__device__ __forceinline__ void ldmBT(unsigned* r, unsigned a){
    asm volatile("ldmatrix.sync.aligned.m8n8.x4.trans.shared.b16 {%0,%1,%2,%3},[%4];"
        :"=r"(r[0]),"=r"(r[1]),"=r"(r[2]),"=r"(r[3]):"r"(a));
}
__device__ __forceinline__ void mmabf(float* c, const unsigned* a, const unsigned* b){
    asm volatile("mma.sync.aligned.m16n8k16.row.col.f32.bf16.bf16.f32 "
        "{%0,%1,%2,%3},{%4,%5,%6,%7},{%8,%9},{%0,%1,%2,%3};"
        :"+f"(c[0]),"+f"(c[1]),"+f"(c[2]),"+f"(c[3])
        :"r"(a[0]),"r"(a[1]),"r"(a[2]),"r"(a[3]),"r"(b[0]),"r"(b[1]));
}
__device__ __forceinline__ unsigned packbf(float a, float b){
    __nv_bfloat16 ha=__float2bfloat16(a), hb=__float2bfloat16(b);
    return (unsigned)__bfloat16_as_ushort(ha) | ((unsigned)__bfloat16_as_ushort(hb)<<16);
}

// ---- 1x1 conv + BN + ReLU ----
template<int OC>
__global__ __launch_bounds__(256)
void conv1x1_k(const float* __restrict__ x, const float* __restrict__ W,
               const float* __restrict__ S, const float* __restrict__ Bb,
               float* __restrict__ out)
{
    constexpr int P = OC + 4, OCG = OC/8, PXG = 256/OCG;
    __shared__ float ws[64*P];
    const int c = blockIdx.y;
    const float* Wc = W + (size_t)c*OC*64;
    for (int l = threadIdx.x; l < 64*OC; l += 256) {
        int oc = l>>6, ic = l&63; ws[ic*P+oc] = Wc[(size_t)oc*64+ic];
    }
    __syncthreads();
    const int ocg = threadIdx.x / PXG, pxg = threadIdx.x % PXG;
    const int px = blockIdx.x*(PXG*8) + pxg*8;
    const float* X = x + (size_t)c*64*HWPX + px;
    ull acc[4][8];
#pragma unroll
    for (int p=0;p<4;p++)
#pragma unroll
        for (int j=0;j<8;j++) acc[p][j]=0ull;
#pragma unroll 4
    for (int ic=0; ic<64; ic++) {
        float4 xa = *(const float4*)(X + (size_t)ic*HWPX);
        float4 xb = *(const float4*)(X + (size_t)ic*HWPX + 4);
        ull sv[8] = { splat2(xa.x),splat2(xa.y),splat2(xa.z),splat2(xa.w),
                      splat2(xb.x),splat2(xb.y),splat2(xb.z),splat2(xb.w) };
        const ull* wp = (const ull*)(ws + ic*P + ocg*8);
        ull w0=wp[0],w1=wp[1],w2=wp[2],w3=wp[3];
#pragma unroll
        for (int j=0;j<8;j++) {
            acc[0][j]=ffma2(w0,sv[j],acc[0][j]); acc[1][j]=ffma2(w1,sv[j],acc[1][j]);
            acc[2][j]=ffma2(w2,sv[j],acc[2][j]); acc[3][j]=ffma2(w3,sv[j],acc[3][j]);
        }
    }
    const float* Sc = S + (size_t)c*OC + ocg*8;
    const float* Bc = Bb + (size_t)c*OC + ocg*8;
    float* O = out + (size_t)c*OC*HWPX + px;
#pragma unroll
    for (int p=0;p<4;p++) {
        float s0=Sc[2*p],s1=Sc[2*p+1],b0=Bc[2*p],b1=Bc[2*p+1];
        float r0[8],r1[8];
#pragma unroll
        for (int j=0;j<8;j++) {
            float2 v = unpk(acc[p][j]);
            r0[j]=fmaxf(v.x*s0+b0,0.f); r1[j]=fmaxf(v.y*s1+b1,0.f);
        }
        float* O0 = O + (size_t)(ocg*8+2*p)*HWPX;
        float* O1 = O + (size_t)(ocg*8+2*p+1)*HWPX;
        *(float4*)O0     = make_float4(r0[0],r0[1],r0[2],r0[3]);
        *(float4*)(O0+4) = make_float4(r0[4],r0[5],r0[6],r0[7]);
        *(float4*)O1     = make_float4(r1[0],r1[1],r1[2],r1[3]);
        *(float4*)(O1+4) = make_float4(r1[4],r1[5],r1[6],r1[7]);
    }
}

__global__ void rbar_k(const float* __restrict__ relb)
{
    int idx = blockIdx.x*64 + threadIdx.x;
    if (idx >= NCLS*64) return;
    int c = idx>>6, k = idx&63, ky = k>>3, kx = k&7;
    float s = 0.f;
    for (int q=0;q<64;q++) {
        int qy=q>>3, qx=q&7;
        const float* p = relb + (size_t)c*900 + ((qy-ky+7)*15 + (qx-kx+7))*4;
        s += p[0]+p[1]+p[2]+p[3];
    }
    g_rbar[idx] = s * (1.f/256.f);
}

__global__ void mask_k()
{
    __shared__ float qw[64*65], kw[64*65], qs[64];
    const int c = blockIdx.y, n = blockIdx.x;
    const int wy = n>>5, wx = n&31, t = threadIdx.x;
    const int px = (wy*8 + (t>>3))*IMG + wx*8 + (t&7);
    const float* Q = g_qk + (size_t)c*128*HWPX;
    for (int ch=0; ch<64; ch++) {
        qw[ch*65+t] = Q[(size_t)ch*HWPX + px];
        kw[ch*65+t] = Q[(size_t)(64+ch)*HWPX + px];
    }
    __syncthreads();
    float s = 0.f;
    for (int q=0;q<64;q++) s += qw[t*65+q];
    qs[t] = s;
    __syncthreads();
    float m = 0.f;
    for (int ch=0;ch<64;ch++) m += qs[ch]*kw[ch*65+t];
    g_mask[(size_t)c*65536 + n*64 + t] = m*(0.25f/256.f) + g_rbar[c*64+t];
}

__global__ void good_k()
{
    int idx = blockIdx.x*256 + threadIdx.x;
    float m[NCLS], mx = -1e30f;
#pragma unroll
    for (int c=0;c<NCLS;c++) { m[c]=g_mask[(size_t)c*65536+idx]; mx=fmaxf(mx,m[c]); }
#pragma unroll
    for (int c=0;c<NCLS;c++) g_good[(size_t)c*65536+idx] = (m[c]==mx)?1.f:-1.f;
}

__global__ __launch_bounds__(256)
void attn_k(const float* __restrict__ x, const float* __restrict__ relb,
            float* __restrict__ xo)
{
    __shared__ float buf[4*64*16];
    __shared__ float rel_s[900];
    __shared__ float gg[64];
    const int c = blockIdx.y, n = blockIdx.x;
    const int wy = n>>5, wx = n&31, tid = threadIdx.x;
    for (int l=tid; l<900; l+=256) rel_s[l] = relb[(size_t)c*900+l];
    if (tid < 64) gg[tid] = g_good[(size_t)c*65536 + n*64 + tid];
    const float* Q = g_qk + (size_t)c*128*HWPX;
    for (int l=tid; l<4096; l+=256) {
        int pos=l&63, ch=l>>6;
        int gpx = (wy*8+(pos>>3))*IMG + wx*8 + (pos&7);
        buf[((ch>>4)*64+pos)*16 + (ch&15)] = Q[(size_t)ch*HWPX + gpx];
    }
    __syncthreads();
    const int h = tid>>6, q = tid&63;
    float qv[16];
#pragma unroll
    for (int d=0;d<16;d++) qv[d] = buf[(h*64+q)*16+d];
    __syncthreads();
    for (int l=tid; l<4096; l+=256) {
        int pos=l&63, ch=l>>6;
        int gpx = (wy*8+(pos>>3))*IMG + wx*8 + (pos&7);
        buf[((ch>>4)*64+pos)*16 + (ch&15)] = Q[(size_t)(64+ch)*HWPX + gpx];
    }
    __syncthreads();
    float dt[64];
    const int qy=q>>3, qx=q&7;
#pragma unroll
    for (int k=0;k<64;k++) {
        const float4* kp = (const float4*)(buf + (h*64+k)*16);
        float4 k0=kp[0],k1=kp[1],k2=kp[2],k3=kp[3];
        float a = qv[0]*k0.x+qv[1]*k0.y+qv[2]*k0.z+qv[3]*k0.w
                + qv[4]*k1.x+qv[5]*k1.y+qv[6]*k1.z+qv[7]*k1.w
                + qv[8]*k2.x+qv[9]*k2.y+qv[10]*k2.z+qv[11]*k2.w
                + qv[12]*k3.x+qv[13]*k3.y+qv[14]*k3.z+qv[15]*k3.w;
        int ky=k>>3, kx=k&7;
        dt[k] = a*0.25f + rel_s[((qy-ky+7)*15+(qx-kx+7))*4 + h];
    }
    float mx = -1e30f;
#pragma unroll
    for (int k=0;k<64;k++) mx = fmaxf(mx, dt[k]);
    float sum = 0.f;
#pragma unroll
    for (int k=0;k<64;k++) { dt[k]=__expf(dt[k]-mx); sum+=dt[k]; }
    float sc = gg[q]/sum;
#pragma unroll
    for (int k=0;k<64;k++) dt[k] *= sc*gg[k];
    __syncthreads();
    const float* V = g_v + (size_t)c*64*HWPX;
    for (int l=tid; l<4096; l+=256) {
        int pos=l&63, ch=l>>6;
        int gpx = (wy*8+(pos>>3))*IMG + wx*8 + (pos&7);
        buf[((ch>>4)*64+pos)*16 + (ch&15)] = V[(size_t)ch*HWPX + gpx];
    }
    __syncthreads();
    float o[16];
#pragma unroll
    for (int d=0;d<16;d++) o[d]=0.f;
#pragma unroll
    for (int k=0;k<64;k++) {
        float a = dt[k];
        const float4* vp = (const float4*)(buf + (h*64+k)*16);
        float4 v0=vp[0],v1=vp[1],v2=vp[2],v3=vp[3];
        o[0]+=a*v0.x; o[1]+=a*v0.y; o[2]+=a*v0.z; o[3]+=a*v0.w;
        o[4]+=a*v1.x; o[5]+=a*v1.y; o[6]+=a*v1.z; o[7]+=a*v1.w;
        o[8]+=a*v2.x; o[9]+=a*v2.y; o[10]+=a*v2.z; o[11]+=a*v2.w;
        o[12]+=a*v3.x; o[13]+=a*v3.y; o[14]+=a*v3.z; o[15]+=a*v3.w;
    }
    const int gpx = (wy*8+qy)*IMG + wx*8 + qx;
    const float* X = x + (size_t)c*64*HWPX;
    float* O = xo + (size_t)c*64*HWPX;
    float r[16];
#pragma unroll
    for (int d=0;d<16;d++) {
        size_t off = (size_t)(h*16+d)*HWPX + gpx;
        r[d] = X[off] + o[d];
        O[off] = r[d];
    }
    unsigned ph[8], pl[8];
#pragma unroll
    for (int d=0;d<8;d++) {
        float a = r[2*d], b = r[2*d+1];
        __nv_bfloat16 ha=__float2bfloat16(a), hb=__float2bfloat16(b);
        float la = a - __bfloat162float(ha), lb = b - __bfloat162float(hb);
        ph[d] = (unsigned)__bfloat16_as_ushort(ha) | ((unsigned)__bfloat16_as_ushort(hb)<<16);
        pl[d] = packbf(la, lb);
    }
    size_t co = ((size_t)(c<<16) + gpx)*64 + h*16;
    *(uint4*)(g_h0+co)   = make_uint4(ph[0],ph[1],ph[2],ph[3]);
    *(uint4*)(g_h0+co+8) = make_uint4(ph[4],ph[5],ph[6],ph[7]);
    *(uint4*)(g_l0+co)   = make_uint4(pl[0],pl[1],pl[2],pl[3]);
    *(uint4*)(g_l0+co+8) = make_uint4(pl[4],pl[5],pl[6],pl[7]);
}

// ---- weight prep: f32 [cs][oc][ic][3][3] -> bf16 hi/lo [cs][kyx][ic][oc] ----
__global__ void wprep_k(const float* __restrict__ W)
{
    int i = blockIdx.x*256 + threadIdx.x;
    if (i >= 36*9*64*64) return;
    int kyx = i % 9; int t = i / 9;
    int ic = t & 63; t >>= 6;
    int oc = t & 63; int cs = t >> 6;
    float w = W[(((size_t)cs*64 + oc)*64 + ic)*9 + kyx];
    __nv_bfloat16 h = __float2bfloat16(w);
    float l = w - __bfloat162float(h);
    size_t d = ((size_t)cs*9 + kyx)*4096 + ic*64 + oc;
    g_wbh[d] = h; g_wbl[d] = __float2bfloat16(l);
}

// ---- conv3x3 via bf16 mma 3-pass split; K=64 stages (one per kyx) ----
#define C3_HALF 41984
#define WSTG    16384
#define C3_SMEMB (2*C3_HALF + 2*WSTG)   // 116736
__global__ __launch_bounds__(512,1)
void c3mma_k(const __nv_bfloat16* __restrict__ srcH, const __nv_bfloat16* __restrict__ srcL,
             const float* __restrict__ S, const float* __restrict__ Bb,
             float* __restrict__ dstF, __nv_bfloat16* __restrict__ dstH,
             __nv_bfloat16* __restrict__ dstL, int nsub, int sub0)
{
    extern __shared__ char sm[];
    char* inH = sm; char* inL = sm + C3_HALF;
    char* wb  = sm + 2*C3_HALF;                 // [buf2][WSTG: hi 8KB + lo 8KB]
    const int cls = blockIdx.z, ty = blockIdx.y, tx = blockIdx.x;
    const int tid = threadIdx.x, lane = tid&31, wid = tid>>5;
    const int mb = wid&7, nb = wid>>3;

    // stage halo 18x18 px x 64ic (swizzled rows of 128B)
    for (int idx = tid; idx < 324*8; idx += 512) {
        int p = idx>>3, ch = idx&7;
        int gy = ty*16 - 1 + p/18, gx = tx*16 - 1 + p%18;
        unsigned d = SWZ(p*128 + ch*16);
        if ((unsigned)gy<256u && (unsigned)gx<256u) {
            size_t so = ((size_t)(cls<<16) + gy*IMG + gx)*64 + ch*8;
            cp16(inH+d, srcH+so);
            cp16(inL+d, srcL+so);
        } else {
            *(uint4*)(inH+d) = make_uint4(0,0,0,0);
            *(uint4*)(inL+d) = make_uint4(0,0,0,0);
        }
    }
    asm volatile("cp.async.commit_group;");
    asm volatile("cp.async.wait_group 0;");
    __syncthreads();

    const int rl   = (lane&7) + ((lane>>3)&1)*8;
    const int ksel = (lane>>4)*16;
    const int px0 = mb*32 + rl, px1 = px0 + 16;
    const int pr0 = px0>>4, pc0 = px0&15, pr1 = px1>>4, pc1 = px1&15;
    const int kr   = (lane&7) + ((lane>>3)&1)*8;
    const int jsel = (lane>>4)&1;

    float osum[2][4][4];
#pragma unroll
    for (int a=0;a<2;a++)
#pragma unroll
        for (int b=0;b<4;b++)
#pragma unroll
            for (int j=0;j<4;j++) osum[a][b][j]=0.f;

    for (int sub=0; sub<nsub; sub++) {
        const int cs = cls*6 + sub0 + sub;
        const __nv_bfloat16* WH = g_wbh + (size_t)cs*9*4096;
        const __nv_bfloat16* WL = g_wbl + (size_t)cs*9*4096;
        // stage one kyx: 64ic x 64oc hi (8KB) + lo (8KB)
        auto stagew = [&](int buf, int kyx){
#pragma unroll
            for (int t=0;t<2;t++){
                int idx = tid + t*512;
                int half = idx>>9, r = (idx>>3)&63, ch = idx&7;
                const __nv_bfloat16* sp = (half?WL:WH) + (size_t)kyx*4096 + r*64 + ch*8;
                cp16(wb + buf*WSTG + half*8192 + SWZ(r*128+ch*16), sp);
            }
        };
        float c[2][4][4];
#pragma unroll
        for (int a=0;a<2;a++)
#pragma unroll
            for (int b=0;b<4;b++)
#pragma unroll
                for (int j=0;j<4;j++) c[a][b][j]=0.f;
        stagew(0, 0);
        asm volatile("cp.async.commit_group;");
        for (int st=0; st<9; st++) {
            char* cw = wb + (st&1)*WSTG;
            if (st < 8) {
                stagew((st+1)&1, st+1);
                asm volatile("cp.async.commit_group;");
                asm volatile("cp.async.wait_group 1;");
            } else {
                asm volatile("cp.async.wait_group 0;");
            }
            __syncthreads();
            const int dy = st/3, dx = st - dy*3;
#pragma unroll
            for (int kc=0; kc<4; kc++) {
                const unsigned ao0 = SWZ(((pr0+dy)*18 + pc0+dx)*128 + kc*32 + ksel);
                const unsigned ao1 = SWZ(((pr1+dy)*18 + pc1+dx)*128 + kc*32 + ksel);
                unsigned ah0[4],al0[4],ah1[4],al1[4];
                ldmA(ah0, sptr(inH+ao0)); ldmA(al0, sptr(inL+ao0));
                ldmA(ah1, sptr(inH+ao1)); ldmA(al1, sptr(inL+ao1));
                const unsigned bo0 = SWZ((kc*16+kr)*128 + (nb*4 + jsel)*16);
                const unsigned bo1 = SWZ((kc*16+kr)*128 + (nb*4 + 2 + jsel)*16);
                unsigned bhA[4],bhB[4],blA[4],blB[4];
                ldmBT(bhA, sptr(cw+bo0));       ldmBT(bhB, sptr(cw+bo1));
                ldmBT(blA, sptr(cw+8192+bo0));  ldmBT(blB, sptr(cw+8192+bo1));
                const unsigned* BH[4] = { bhA, bhA+2, bhB, bhB+2 };
                const unsigned* BL[4] = { blA, blA+2, blB, blB+2 };
#pragma unroll
                for (int nt=0; nt<4; nt++) {
                    mmabf(c[0][nt], ah0, BH[nt]);
                    mmabf(c[0][nt], ah0, BL[nt]);
                    mmabf(c[0][nt], al0, BH[nt]);
                    mmabf(c[1][nt], ah1, BH[nt]);
                    mmabf(c[1][nt], ah1, BL[nt]);
                    mmabf(c[1][nt], al1, BH[nt]);
                }
            }
            __syncthreads();
        }
        // BN + clip6 + accumulate
#pragma unroll
        for (int nt=0; nt<4; nt++) {
            int oc = nb*32 + nt*8 + (lane&3)*2;
            float s0 = S[(size_t)cs*64+oc], s1 = S[(size_t)cs*64+oc+1];
            float b0 = Bb[(size_t)cs*64+oc], b1 = Bb[(size_t)cs*64+oc+1];
#pragma unroll
            for (int mt=0; mt<2; mt++)
#pragma unroll
                for (int p=0; p<2; p++) {
                    osum[mt][nt][2*p]   += fminf(fmaxf(c[mt][nt][2*p]*s0+b0, 0.f), 6.f);
                    osum[mt][nt][2*p+1] += fminf(fmaxf(c[mt][nt][2*p+1]*s1+b1, 0.f), 6.f);
                }
        }
    }
    // write f32 (+ optional hi/lo channel-last)
#pragma unroll
    for (int mt=0; mt<2; mt++)
#pragma unroll
        for (int p=0; p<2; p++) {
            int pxl = mb*32 + mt*16 + (lane>>2) + p*8;
            int gp = (ty*16 + (pxl>>4))*IMG + tx*16 + (pxl&15);
#pragma unroll
            for (int nt=0; nt<4; nt++) {
                int oc = nb*32 + nt*8 + (lane&3)*2;
                float v0 = osum[mt][nt][2*p], v1 = osum[mt][nt][2*p+1];
                dstF[((size_t)(cls*64+oc))*HWPX + gp]   = v0;
                dstF[((size_t)(cls*64+oc+1))*HWPX + gp] = v1;
                if (dstH) {
                    size_t co = ((size_t)(cls<<16) + gp)*64 + oc;
                    __nv_bfloat16 h0=__float2bfloat16(v0), h1=__float2bfloat16(v1);
                    float l0 = v0-__bfloat162float(h0), l1 = v1-__bfloat162float(h1);
                    *(unsigned*)(dstH+co) = (unsigned)__bfloat16_as_ushort(h0)
                                          | ((unsigned)__bfloat16_as_ushort(h1)<<16);
                    *(unsigned*)(dstL+co) = packbf(l0, l1);
                }
            }
        }
}

// ---- cat 1x1 conv + BN + residual + relu -> d_out ----
__global__ __launch_bounds__(256)
void cat_k(const float* __restrict__ cw, const float* __restrict__ cs,
           const float* __restrict__ cb, float* __restrict__ out)
{
    __shared__ float ws[64*68];
    const int c = blockIdx.y, tid = threadIdx.x;
    const int ocg = tid>>5, pxg = tid&31;
    const int px = blockIdx.x*256 + pxg*8;
    ull acc[4][8];
#pragma unroll
    for (int p=0;p<4;p++)
#pragma unroll
        for (int j=0;j<8;j++) acc[p][j]=0ull;
    const float* srcs[3] = { g_x112 + (size_t)c*64*HWPX,
                             g_x223 + (size_t)c*64*HWPX,
                             g_x33  + (size_t)c*64*HWPX };
    for (int s=0; s<3; s++) {
        __syncthreads();
        for (int l=tid; l<4096; l+=256) {
            int oc=l>>6, ic=l&63;
            ws[ic*68+oc] = cw[(size_t)c*64*192 + oc*192 + s*64 + ic];
        }
        __syncthreads();
        const float* X = srcs[s] + px;
#pragma unroll 4
        for (int ic=0; ic<64; ic++) {
            float4 xa = *(const float4*)(X + (size_t)ic*HWPX);
            float4 xb = *(const float4*)(X + (size_t)ic*HWPX + 4);
            ull sv[8] = { splat2(xa.x),splat2(xa.y),splat2(xa.z),splat2(xa.w),
                          splat2(xb.x),splat2(xb.y),splat2(xb.z),splat2(xb.w) };
            const ull* wp = (const ull*)(ws + ic*68 + ocg*8);
            ull w0=wp[0],w1=wp[1],w2=wp[2],w3=wp[3];
#pragma unroll
            for (int j=0;j<8;j++) {
                acc[0][j]=ffma2(w0,sv[j],acc[0][j]); acc[1][j]=ffma2(w1,sv[j],acc[1][j]);
                acc[2][j]=ffma2(w2,sv[j],acc[2][j]); acc[3][j]=ffma2(w3,sv[j],acc[3][j]);
            }
        }
    }
    const float* Sc = cs + (size_t)c*64 + ocg*8;
    const float* Bc = cb + (size_t)c*64 + ocg*8;
    const float* XO = g_xo + (size_t)c*64*HWPX + px;
    float* O = out + (size_t)c*64*HWPX + px;
#pragma unroll
    for (int p=0;p<4;p++) {
        float s0=Sc[2*p],s1=Sc[2*p+1],b0=Bc[2*p],b1=Bc[2*p+1];
#pragma unroll
        for (int j=0;j<8;j++) {
            float2 v = unpk(acc[p][j]);
            size_t o0 = (size_t)(ocg*8+2*p)*HWPX + j;
            size_t o1 = (size_t)(ocg*8+2*p+1)*HWPX + j;
            O[o0] = fmaxf(v.x*s0+b0 + XO[o0], 0.f);
            O[o1] = fmaxf(v.y*s1+b1 + XO[o1], 0.f);
        }
    }
}

extern "C" void kernel_launch(void* const* d_in, const int* in_sizes, int n_in,
                              void* d_out, int out_size)
{
    const float* x    = (const float*)d_in[0];
    const float* qkw  = (const float*)d_in[1];
    const float* qks  = (const float*)d_in[2];
    const float* qkb  = (const float*)d_in[3];
    const float* relb = (const float*)d_in[4];
    const float* wvw  = (const float*)d_in[5];
    const float* wvs  = (const float*)d_in[6];
    const float* wvb  = (const float*)d_in[7];
    const float* mmsw = (const float*)d_in[8];
    const float* mmss = (const float*)d_in[9];
    const float* mmsb = (const float*)d_in[10];
    const float* catw = (const float*)d_in[11];
    const float* cats = (const float*)d_in[12];
    const float* catb = (const float*)d_in[13];
    float* out = (float*)d_out;

    float *qk, *v, *xo, *a112, *b223, *c33;
    cudaGetSymbolAddress((void**)&qk,   g_qk);
    cudaGetSymbolAddress((void**)&v,    g_v);
    cudaGetSymbolAddress((void**)&xo,   g_xo);
    cudaGetSymbolAddress((void**)&a112, g_x112);
    cudaGetSymbolAddress((void**)&b223, g_x223);
    cudaGetSymbolAddress((void**)&c33,  g_x33);
    __nv_bfloat16 *h0,*l0,*h1,*l1,*h2,*l2;
    cudaGetSymbolAddress((void**)&h0, g_h0); cudaGetSymbolAddress((void**)&l0, g_l0);
    cudaGetSymbolAddress((void**)&h1, g_h1); cudaGetSymbolAddress((void**)&l1, g_l1);
    cudaGetSymbolAddress((void**)&h2, g_h2); cudaGetSymbolAddress((void**)&l2, g_l2);

    cudaFuncSetAttribute(c3mma_k, cudaFuncAttributeMaxDynamicSharedMemorySize, C3_SMEMB);

    conv1x1_k<128><<<dim3(512, NCLS), 256>>>(x, qkw, qks, qkb, qk);
    conv1x1_k<64> <<<dim3(256, NCLS), 256>>>(x, wvw, wvs, wvb, v);
    rbar_k<<<NCLS, 64>>>(relb);
    mask_k<<<dim3(1024, NCLS), 64>>>();
    good_k<<<256, 256>>>();
    attn_k<<<dim3(1024, NCLS), 256>>>(x, relb, xo);
    wprep_k<<<(36*9*64*64 + 255)/256, 256>>>(mmsw);
    c3mma_k<<<dim3(16, 16, NCLS), 512, C3_SMEMB>>>(h0, l0, mmss, mmsb, a112, h1, l1, 3, 0);
    c3mma_k<<<dim3(16, 16, NCLS), 512, C3_SMEMB>>>(h1, l1, mmss, mmsb, b223, h2, l2, 2, 3);
    c3mma_k<<<dim3(16, 16, NCLS), 512, C3_SMEMB>>>(h2, l2, mmss, mmsb, c33, (__nv_bfloat16*)0, (__nv_bfloat16*)0, 1, 5);
    cat_k<<<dim3(256, NCLS), 256>>>(catw, cats, catb, out);
}